// round 1
// baseline (speedup 1.0000x reference)
#include <cuda_runtime.h>
#include <math.h>

#define MAXN 50048
#define MAXE 800000
#define MAXT (MAXE + MAXN)

// ---- scratch (static __device__, no allocations) ----
__device__ __align__(16) float g_xw1[MAXN * 256];
__device__ __align__(16) float g_als1[MAXN * 4];
__device__ __align__(16) float g_ald1[MAXN * 4];
__device__ float g_loop_sum[MAXN];
__device__ float g_loop_cnt[MAXN];
__device__ int   g_dcnt[MAXN];
__device__ int   g_off[MAXN + 1];
__device__ int   g_cur[MAXN];
__device__ int   g_adj[MAXT];
__device__ __align__(16) float g_w1[MAXT * 4];
__device__ __align__(16) float g_h1[MAXN * 256];
__device__ __align__(16) float g_xw2[MAXN * 64];
__device__ float g_als2[MAXN];
__device__ float g_ald2[MAXN];
__device__ float g_w2[MAXT];
__device__ __align__(16) float g_out2[MAXN * 64];
__device__ float g_ce[5];
__device__ float g_pool[264];   // [0:256) zsum[4][64], [256:260) cnt, [260:264) cf

__device__ __forceinline__ float lrelu(float x) { return x > 0.f ? x : 0.2f * x; }
__device__ __forceinline__ float eluf(float x)  { return x > 0.f ? x : (expf(x) - 1.f); }

// ---- precompute per-head edge-attention constants ----
__global__ void k_prep(const float* __restrict__ We1, const float* __restrict__ ae1,
                       const float* __restrict__ We2, const float* __restrict__ ae2) {
    __shared__ float s[5];
    int t = threadIdx.x;
    if (t < 5) s[t] = 0.f;
    __syncthreads();
    atomicAdd(&s[t >> 6], We1[t] * ae1[t]);           // t in [0,256)
    if (t < 64) atomicAdd(&s[4], We2[t] * ae2[t]);
    __syncthreads();
    if (t < 5) g_ce[t] = s[t];
}

// ---- per-dst degree (incl. self loop) + self-loop attr sums ----
__global__ void k_degloop(const int* __restrict__ dst, const float* __restrict__ ea,
                          int e, int n) {
    int idx = blockIdx.x * blockDim.x + threadIdx.x;
    if (idx >= e + n) return;
    int d;
    if (idx < e) {
        d = dst[idx];
        atomicAdd(&g_loop_sum[d], ea[idx]);
        atomicAdd(&g_loop_cnt[d], 1.f);
    } else {
        d = idx - e;
    }
    atomicAdd(&g_dcnt[d], 1);
}

// ---- single-block scan over degrees -> offsets + cursor copy ----
__global__ void k_scan(int n) {
    __shared__ int part[1024];
    int t = threadIdx.x;
    int chunk = (n + 1023) >> 10;
    int beg = t * chunk, end = min(beg + chunk, n);
    int s = 0;
    for (int i = beg; i < end; i++) s += g_dcnt[i];
    part[t] = s;
    __syncthreads();
    for (int off = 1; off < 1024; off <<= 1) {
        int v = (t >= off) ? part[t - off] : 0;
        __syncthreads();
        part[t] += v;
        __syncthreads();
    }
    int run = (t == 0) ? 0 : part[t - 1];
    for (int i = beg; i < end; i++) {
        g_off[i] = run; g_cur[i] = run;
        run += g_dcnt[i];
    }
    if (t == 0) g_off[n] = part[1023];
}

// ---- fill adjacency (edges grouped by dst) ----
__global__ void k_fill(const int* __restrict__ dst, int e, int n) {
    int idx = blockIdx.x * blockDim.x + threadIdx.x;
    if (idx >= e + n) return;
    int d = (idx < e) ? dst[idx] : (idx - e);
    int p = atomicAdd(&g_cur[d], 1);
    g_adj[p] = idx;
}

// ---- xw1 = x @ W1 (+ fused al_src1 / al_dst1), one warp per node ----
__global__ void k_xw1(const float* __restrict__ x, const float* __restrict__ W1,
                      const float* __restrict__ as1, const float* __restrict__ ad1, int n) {
    __shared__ float sW[7 * 256];
    __shared__ float sA[256];
    __shared__ float sB[256];
    int t = threadIdx.x;
    for (int i = t; i < 7 * 256; i += blockDim.x) sW[i] = W1[i];
    if (t < 256) { sA[t] = as1[t]; sB[t] = ad1[t]; }
    __syncthreads();
    int warp = (blockIdx.x * blockDim.x + t) >> 5;
    int lane = t & 31;
    if (warp >= n) return;
    float xv[7];
#pragma unroll
    for (int i = 0; i < 7; i++) xv[i] = x[warp * 7 + i];
    float accs[4] = {0, 0, 0, 0};
    float accd[4] = {0, 0, 0, 0};
#pragma unroll
    for (int k = 0; k < 8; k++) {
        int c = lane + k * 32;
        float v = 0.f;
#pragma unroll
        for (int i = 0; i < 7; i++) v = fmaf(xv[i], sW[i * 256 + c], v);
        g_xw1[(size_t)warp * 256 + c] = v;
        accs[k >> 1] = fmaf(v, sA[c], accs[k >> 1]);
        accd[k >> 1] = fmaf(v, sB[c], accd[k >> 1]);
    }
#pragma unroll
    for (int h = 0; h < 4; h++) {
        float vs = accs[h], vd = accd[h];
#pragma unroll
        for (int o = 16; o; o >>= 1) {
            vs += __shfl_down_sync(0xffffffffu, vs, o);
            vd += __shfl_down_sync(0xffffffffu, vd, o);
        }
        if (lane == 0) { g_als1[warp * 4 + h] = vs; g_ald1[warp * 4 + h] = vd; }
    }
}

// ---- conv1 edge attention weights (no atomics) ----
__global__ void k_att1(const int* __restrict__ src, const int* __restrict__ dst,
                       const float* __restrict__ ea, int e, int n) {
    int idx = blockIdx.x * blockDim.x + threadIdx.x;
    if (idx >= e + n) return;
    int s, d; float a;
    if (idx < e) { s = src[idx]; d = dst[idx]; a = ea[idx]; }
    else { s = d = idx - e; a = g_loop_sum[s] / fmaxf(g_loop_cnt[s], 1.f); }
    float4 ls = *reinterpret_cast<const float4*>(&g_als1[s * 4]);
    float4 ld = *reinterpret_cast<const float4*>(&g_ald1[d * 4]);
    float4 w;
    w.x = expf(lrelu(ls.x + ld.x + a * g_ce[0]));
    w.y = expf(lrelu(ls.y + ld.y + a * g_ce[1]));
    w.z = expf(lrelu(ls.z + ld.z + a * g_ce[2]));
    w.w = expf(lrelu(ls.w + ld.w + a * g_ce[3]));
    *reinterpret_cast<float4*>(&g_w1[(size_t)idx * 4]) = w;
}

// ---- conv1 gather-aggregate, 64 threads/node, fused softmax-norm + bias + ELU ----
__global__ void k_gather1(const int* __restrict__ src, const float* __restrict__ b1,
                          int e, int n) {
    int gt = blockIdx.x * blockDim.x + threadIdx.x;
    int node = gt >> 6;
    if (node >= n) return;
    int t = gt & 63, h = t >> 4;
    int beg = g_off[node], end = g_off[node + 1];
    float4 acc = make_float4(0, 0, 0, 0);
    float sw = 0.f;
    for (int i = beg; i < end; i++) {
        int eid = g_adj[i];
        int s = (eid < e) ? src[eid] : node;
        float w = g_w1[(size_t)eid * 4 + h];
        float4 v = *reinterpret_cast<const float4*>(&g_xw1[(size_t)s * 256 + t * 4]);
        acc.x = fmaf(w, v.x, acc.x); acc.y = fmaf(w, v.y, acc.y);
        acc.z = fmaf(w, v.z, acc.z); acc.w = fmaf(w, v.w, acc.w);
        sw += w;
    }
    float inv = 1.f / (sw + 1e-16f);
    float4 bb = *reinterpret_cast<const float4*>(&b1[t * 4]);
    float4 o;
    o.x = eluf(acc.x * inv + bb.x); o.y = eluf(acc.y * inv + bb.y);
    o.z = eluf(acc.z * inv + bb.z); o.w = eluf(acc.w * inv + bb.w);
    *reinterpret_cast<float4*>(&g_h1[(size_t)node * 256 + t * 4]) = o;
}

// ---- xw2 = h1 @ W2 (+ fused al_src2/al_dst2). 64 nodes/block, smem-tiled ----
#define XW2_NODES 64
__global__ void k_xw2(const float* __restrict__ W2, const float* __restrict__ as2,
                      const float* __restrict__ ad2, int n) {
    extern __shared__ float sm[];
    float2* sW = reinterpret_cast<float2*>(sm);          // 64KB: W2 as float2 pairs
    float*  srow = sm + 16384;                           // 64KB: 64 rows x 256
    int t = threadIdx.x;                                 // 256 threads
    {
        const float4* w4 = reinterpret_cast<const float4*>(W2);
        float4* d4 = reinterpret_cast<float4*>(sm);
        for (int i = t; i < 4096; i += 256) d4[i] = w4[i];
    }
    int base = blockIdx.x * XW2_NODES;
    int cnt = min(XW2_NODES, n - base);
    {
        const float4* h4 = reinterpret_cast<const float4*>(g_h1 + (size_t)base * 256);
        float4* r4 = reinterpret_cast<float4*>(srow);
        for (int i = t; i < cnt * 64; i += 256) r4[i] = h4[i];
        for (int i = cnt * 64 + t; i < XW2_NODES * 64; i += 256)
            r4[i] = make_float4(0, 0, 0, 0);
    }
    __syncthreads();
    int warp = t >> 5, l = t & 31;
    int nb = warp * 8;
    float a0[8], a1[8];
#pragma unroll
    for (int j = 0; j < 8; j++) { a0[j] = 0.f; a1[j] = 0.f; }
#pragma unroll 4
    for (int k = 0; k < 256; k++) {
        float2 w = sW[k * 32 + l];
#pragma unroll
        for (int j = 0; j < 8; j++) {
            float hv = srow[(nb + j) * 256 + k];
            a0[j] = fmaf(hv, w.x, a0[j]);
            a1[j] = fmaf(hv, w.y, a1[j]);
        }
    }
    float s0 = as2[2 * l], s1 = as2[2 * l + 1];
    float d0 = ad2[2 * l], d1 = ad2[2 * l + 1];
#pragma unroll
    for (int j = 0; j < 8; j++) {
        int node = base + nb + j;
        bool ok = node < n;
        if (ok) {
            float2 o = make_float2(a0[j], a1[j]);
            *reinterpret_cast<float2*>(&g_xw2[(size_t)node * 64 + 2 * l]) = o;
        }
        float vs = a0[j] * s0 + a1[j] * s1;
        float vd = a0[j] * d0 + a1[j] * d1;
#pragma unroll
        for (int o = 16; o; o >>= 1) {
            vs += __shfl_down_sync(0xffffffffu, vs, o);
            vd += __shfl_down_sync(0xffffffffu, vd, o);
        }
        if (l == 0 && ok) { g_als2[node] = vs; g_ald2[node] = vd; }
    }
}

// ---- conv2 edge attention ----
__global__ void k_att2(const int* __restrict__ src, const int* __restrict__ dst,
                       const float* __restrict__ ea, int e, int n) {
    int idx = blockIdx.x * blockDim.x + threadIdx.x;
    if (idx >= e + n) return;
    int s, d; float a;
    if (idx < e) { s = src[idx]; d = dst[idx]; a = ea[idx]; }
    else { s = d = idx - e; a = g_loop_sum[s] / fmaxf(g_loop_cnt[s], 1.f); }
    float lg = g_als2[s] + g_ald2[d] + a * g_ce[4];
    g_w2[idx] = expf(lrelu(lg));
}

// ---- conv2 gather-aggregate, 16 threads/node ----
__global__ void k_gather2(const int* __restrict__ src, int e, int n) {
    int gt = blockIdx.x * blockDim.x + threadIdx.x;
    int node = gt >> 4;
    if (node >= n) return;
    int t = gt & 15;
    int beg = g_off[node], end = g_off[node + 1];
    float4 acc = make_float4(0, 0, 0, 0);
    float sw = 0.f;
    for (int i = beg; i < end; i++) {
        int eid = g_adj[i];
        int s = (eid < e) ? src[eid] : node;
        float w = g_w2[eid];
        float4 v = *reinterpret_cast<const float4*>(&g_xw2[(size_t)s * 64 + t * 4]);
        acc.x = fmaf(w, v.x, acc.x); acc.y = fmaf(w, v.y, acc.y);
        acc.z = fmaf(w, v.z, acc.z); acc.w = fmaf(w, v.w, acc.w);
        sw += w;
    }
    float inv = 1.f / (sw + 1e-16f);
    acc.x *= inv; acc.y *= inv; acc.z *= inv; acc.w *= inv;
    *reinterpret_cast<float4*>(&g_out2[(size_t)node * 64 + t * 4]) = acc;
}

// ---- cluster pooling of out2 (register partials -> smem -> few global atomics) ----
__global__ void k_pool(const int* __restrict__ assign, int n) {
    __shared__ float sz[256];
    int t = threadIdx.x;
    sz[t] = 0.f;
    __syncthreads();
    int ch = (blockIdx.x * blockDim.x + t) & 63;
    float r0 = 0, r1 = 0, r2 = 0, r3 = 0;
    int total = n * 64;
    int stride = gridDim.x * blockDim.x;    // multiple of 64 by construction
    for (int idx = blockIdx.x * blockDim.x + t; idx < total; idx += stride) {
        int node = idx >> 6;
        int a = assign[node];
        float v = g_out2[idx];
        if (a == 0) r0 += v; else if (a == 1) r1 += v; else if (a == 2) r2 += v; else r3 += v;
    }
    atomicAdd(&sz[0 * 64 + ch], r0);
    atomicAdd(&sz[1 * 64 + ch], r1);
    atomicAdd(&sz[2 * 64 + ch], r2);
    atomicAdd(&sz[3 * 64 + ch], r3);
    __syncthreads();
    atomicAdd(&g_pool[t], sz[t]);
}

// ---- cluster counts + cf sums ----
__global__ void k_cnt(const float* __restrict__ x, const int* __restrict__ assign, int n) {
    __shared__ float s[8];
    if (threadIdx.x < 8) s[threadIdx.x] = 0.f;
    __syncthreads();
    int idx = blockIdx.x * blockDim.x + threadIdx.x;
    if (idx < n) {
        int a = assign[idx];
        atomicAdd(&s[a], 1.f);
        atomicAdd(&s[4 + a], x[idx * 7 + 6]);
    }
    __syncthreads();
    if (threadIdx.x < 4) atomicAdd(&g_pool[256 + threadIdx.x], s[threadIdx.x]);
    else if (threadIdx.x < 8) atomicAdd(&g_pool[260 + threadIdx.x - 4], s[threadIdx.x]);
}

// ---- final: means + MLP + softmax + write output (1 block, 64 threads) ----
__global__ void k_final(const float* __restrict__ b2, const float* __restrict__ A1,
                        const float* __restrict__ c1, const float* __restrict__ A2,
                        const float* __restrict__ c2, float* __restrict__ out) {
    __shared__ float z[4][64];
    __shared__ float red[64];
    __shared__ float logits[4];
    __shared__ float probs[4];
    int t = threadIdx.x;
    float cf[4];
#pragma unroll
    for (int k = 0; k < 4; k++) {
        float cn = g_pool[256 + k];
        z[k][t] = (cn > 0.f) ? (g_pool[k * 64 + t] / cn + b2[t]) : 0.f;
        cf[k] = (cn > 0.f) ? (g_pool[260 + k] / cn) : 0.f;
    }
    __syncthreads();
    for (int k = 0; k < 4; k++) {
        float acc = c1[t];
        for (int i = 0; i < 64; i++) acc = fmaf(z[k][i], A1[i * 64 + t], acc);
        acc = fmaf(cf[k], A1[64 * 64 + t], acc);
        acc = fmaxf(acc, 0.f) * A2[t];
        red[t] = acc;
        __syncthreads();
        if (t == 0) {
            float s = 0.f;
            for (int i = 0; i < 64; i++) s += red[i];
            logits[k] = s + c2[0];
        }
        __syncthreads();
    }
    if (t == 0) {
        float m = fmaxf(fmaxf(logits[0], logits[1]), fmaxf(logits[2], logits[3]));
        float e0 = expf(logits[0] - m), e1 = expf(logits[1] - m);
        float e2 = expf(logits[2] - m), e3 = expf(logits[3] - m);
        float inv = 1.f / (e0 + e1 + e2 + e3);
        probs[0] = e0 * inv; probs[1] = e1 * inv; probs[2] = e2 * inv; probs[3] = e3 * inv;
    }
    __syncthreads();
    if (t < 4) out[t] = probs[t];
#pragma unroll
    for (int k = 0; k < 4; k++) out[4 + k * 64 + t] = z[k][t];
}

extern "C" void kernel_launch(void* const* d_in, const int* in_sizes, int n_in,
                              void* d_out, int out_size) {
    const float* x    = (const float*)d_in[0];
    const int*   ei   = (const int*)d_in[1];
    const float* ea   = (const float*)d_in[2];
    const int*   assign = (const int*)d_in[3];
    const float* W1   = (const float*)d_in[4];
    const float* as1  = (const float*)d_in[5];
    const float* ad1  = (const float*)d_in[6];
    const float* We1  = (const float*)d_in[7];
    const float* ae1  = (const float*)d_in[8];
    const float* b1   = (const float*)d_in[9];
    const float* W2   = (const float*)d_in[10];
    const float* as2  = (const float*)d_in[11];
    const float* ad2  = (const float*)d_in[12];
    const float* We2  = (const float*)d_in[13];
    const float* ae2  = (const float*)d_in[14];
    const float* b2   = (const float*)d_in[15];
    const float* A1   = (const float*)d_in[16];
    const float* c1   = (const float*)d_in[17];
    const float* A2   = (const float*)d_in[18];
    const float* c2   = (const float*)d_in[19];
    float* out = (float*)d_out;

    int n = in_sizes[0] / 7;
    int e = in_sizes[2];
    const int* src = ei;
    const int* dst = ei + e;
    int tot = e + n;

    void *p_ls, *p_lc, *p_dc, *p_pool;
    cudaGetSymbolAddress(&p_ls, g_loop_sum);
    cudaGetSymbolAddress(&p_lc, g_loop_cnt);
    cudaGetSymbolAddress(&p_dc, g_dcnt);
    cudaGetSymbolAddress(&p_pool, g_pool);
    cudaMemsetAsync(p_ls, 0, (size_t)n * 4, 0);
    cudaMemsetAsync(p_lc, 0, (size_t)n * 4, 0);
    cudaMemsetAsync(p_dc, 0, (size_t)n * 4, 0);
    cudaMemsetAsync(p_pool, 0, 264 * 4, 0);

    k_prep<<<1, 256>>>(We1, ae1, We2, ae2);
    k_degloop<<<(tot + 255) / 256, 256>>>(dst, ea, e, n);
    k_xw1<<<(n + 7) / 8, 256>>>(x, W1, as1, ad1, n);
    k_scan<<<1, 1024>>>(n);
    k_fill<<<(tot + 255) / 256, 256>>>(dst, e, n);
    k_att1<<<(tot + 255) / 256, 256>>>(src, dst, ea, e, n);
    k_gather1<<<(n * 64 + 255) / 256, 256>>>(src, b1, e, n);

    cudaFuncSetAttribute(k_xw2, cudaFuncAttributeMaxDynamicSharedMemorySize, 131072);
    k_xw2<<<(n + XW2_NODES - 1) / XW2_NODES, 256, 131072>>>(W2, as2, ad2, n);

    k_att2<<<(tot + 255) / 256, 256>>>(src, dst, ea, e, n);
    k_gather2<<<(n * 16 + 255) / 256, 256>>>(src, e, n);
    k_pool<<<1184, 256>>>(assign, n);
    k_cnt<<<(n + 255) / 256, 256>>>(x, assign, n);
    k_final<<<1, 64>>>(b2, A1, c1, A2, c2, out);
}

// round 2
// speedup vs baseline: 1.2546x; 1.2546x over previous
#include <cuda_runtime.h>
#include <math.h>

#define MAXN 50048
#define MAXE 800000
#define MAXT (MAXE + MAXN)
#define SCAN_CHUNK 4096

// ---- scratch (static __device__, no allocations) ----
__device__ __align__(16) float g_xw1[MAXN * 256];
__device__ __align__(16) float g_als1[MAXN * 4];
__device__ __align__(16) float g_ald1[MAXN * 4];
__device__ float g_loop_sum[MAXN];
__device__ float g_loop_cnt[MAXN];
__device__ int   g_dcnt[MAXN];
__device__ int   g_off[MAXN + 1];
__device__ int   g_cur[MAXN];
__device__ int   g_adj[MAXT];
__device__ int   g_bsum[64];
__device__ int   g_bpre[64];
__device__ __align__(16) float g_w1[MAXT * 4];
__device__ __align__(16) float g_h1[MAXN * 256];
__device__ __align__(16) float g_xw2[MAXN * 64];
__device__ float g_als2[MAXN];
__device__ float g_ald2[MAXN];
__device__ float g_w2[MAXT];
__device__ __align__(16) float g_out2[MAXN * 64];
__device__ float g_ce[5];
__device__ float g_pool[264];   // [0:256) zsum[4][64], [256:260) cnt, [260:264) cf

__device__ __forceinline__ float lrelu(float x) { return x > 0.f ? x : 0.2f * x; }
__device__ __forceinline__ float eluf(float x)  { return x > 0.f ? x : (expf(x) - 1.f); }

// ---- init: zero scratch + compute per-head edge-attention constants ----
__global__ void k_init(const float* __restrict__ We1, const float* __restrict__ ae1,
                       const float* __restrict__ We2, const float* __restrict__ ae2, int n) {
    int gt = blockIdx.x * blockDim.x + threadIdx.x;
    int stride = gridDim.x * blockDim.x;
    for (int i = gt; i < n; i += stride) {
        g_loop_sum[i] = 0.f;
        g_loop_cnt[i] = 0.f;
        g_dcnt[i] = 0;
    }
    if (gt < 264) g_pool[gt] = 0.f;
    if (blockIdx.x == 0) {
        __shared__ float s[5];
        int t = threadIdx.x;
        if (t < 5) s[t] = 0.f;
        __syncthreads();
        if (t < 256) atomicAdd(&s[t >> 6], We1[t] * ae1[t]);
        if (t < 64) atomicAdd(&s[4], We2[t] * ae2[t]);
        __syncthreads();
        if (t < 5) g_ce[t] = s[t];
    }
}

// ---- per-dst degree (incl. self loop) + self-loop attr sums ----
__global__ void k_degloop(const int* __restrict__ dst, const float* __restrict__ ea,
                          int e, int n) {
    int idx = blockIdx.x * blockDim.x + threadIdx.x;
    if (idx >= e + n) return;
    int d;
    if (idx < e) {
        d = dst[idx];
        atomicAdd(&g_loop_sum[d], ea[idx]);
        atomicAdd(&g_loop_cnt[d], 1.f);
    } else {
        d = idx - e;
    }
    atomicAdd(&g_dcnt[d], 1);
}

// ---- device-wide exclusive scan, stage 1: per-block sums (1024 thr, 4096 elems) ----
__global__ void k_part(int n) {
    int t = threadIdx.x;
    int base = blockIdx.x * SCAN_CHUNK + t * 4;
    int s = 0;
#pragma unroll
    for (int i = 0; i < 4; i++) {
        int idx = base + i;
        if (idx < n) s += g_dcnt[idx];
    }
#pragma unroll
    for (int o = 16; o; o >>= 1) s += __shfl_down_sync(0xffffffffu, s, o);
    __shared__ int ws[32];
    if ((t & 31) == 0) ws[t >> 5] = s;
    __syncthreads();
    if (t < 32) {
        int v = ws[t];
#pragma unroll
        for (int o = 16; o; o >>= 1) v += __shfl_down_sync(0xffffffffu, v, o);
        if (t == 0) g_bsum[blockIdx.x] = v;
    }
}

// ---- stage 2: 1-warp exclusive scan of block sums ----
__global__ void k_scanb(int nb) {
    int t = threadIdx.x;
    int s = (t < nb) ? g_bsum[t] : 0;
    int v = s;
#pragma unroll
    for (int o = 1; o < 32; o <<= 1) {
        int u = __shfl_up_sync(0xffffffffu, v, o);
        if (t >= o) v += u;
    }
    if (t < nb) g_bpre[t] = v - s;
}

// ---- stage 3: block-local scan + fan-out to offsets/cursors ----
__global__ void k_offs(int n, int tot) {
    int t = threadIdx.x;
    int base = blockIdx.x * SCAN_CHUNK + t * 4;
    int v[4];
    int s = 0;
#pragma unroll
    for (int i = 0; i < 4; i++) {
        int idx = base + i;
        v[i] = (idx < n) ? g_dcnt[idx] : 0;
        s += v[i];
    }
    int lane = t & 31, w = t >> 5;
    int ps = s;
#pragma unroll
    for (int o = 1; o < 32; o <<= 1) {
        int u = __shfl_up_sync(0xffffffffu, ps, o);
        if (lane >= o) ps += u;
    }
    __shared__ int ws[32];
    if (lane == 31) ws[w] = ps;
    __syncthreads();
    if (t < 32) {
        int x = ws[t];
#pragma unroll
        for (int o = 1; o < 32; o <<= 1) {
            int u = __shfl_up_sync(0xffffffffu, x, o);
            if (t >= o) x += u;
        }
        ws[t] = x;
    }
    __syncthreads();
    int excl = ps - s + (w ? ws[w - 1] : 0) + g_bpre[blockIdx.x];
#pragma unroll
    for (int i = 0; i < 4; i++) {
        int idx = base + i;
        if (idx < n) {
            g_off[idx] = excl;
            g_cur[idx] = excl;
            excl += v[i];
        }
    }
    if (blockIdx.x == 0 && t == 0) g_off[n] = tot;
}

// ---- fill adjacency (edges grouped by dst) ----
__global__ void k_fill(const int* __restrict__ dst, int e, int n) {
    int idx = blockIdx.x * blockDim.x + threadIdx.x;
    if (idx >= e + n) return;
    int d = (idx < e) ? dst[idx] : (idx - e);
    int p = atomicAdd(&g_cur[d], 1);
    g_adj[p] = idx;
}

// ---- xw1 = x @ W1 (+ fused al_src1 / al_dst1), one warp per node ----
__global__ void k_xw1(const float* __restrict__ x, const float* __restrict__ W1,
                      const float* __restrict__ as1, const float* __restrict__ ad1, int n) {
    __shared__ float sW[7 * 256];
    __shared__ float sA[256];
    __shared__ float sB[256];
    int t = threadIdx.x;
    for (int i = t; i < 7 * 256; i += blockDim.x) sW[i] = W1[i];
    if (t < 256) { sA[t] = as1[t]; sB[t] = ad1[t]; }
    __syncthreads();
    int warp = (blockIdx.x * blockDim.x + t) >> 5;
    int lane = t & 31;
    if (warp >= n) return;
    float xv[7];
#pragma unroll
    for (int i = 0; i < 7; i++) xv[i] = x[warp * 7 + i];
    float accs[4] = {0, 0, 0, 0};
    float accd[4] = {0, 0, 0, 0};
#pragma unroll
    for (int k = 0; k < 8; k++) {
        int c = lane + k * 32;
        float v = 0.f;
#pragma unroll
        for (int i = 0; i < 7; i++) v = fmaf(xv[i], sW[i * 256 + c], v);
        g_xw1[(size_t)warp * 256 + c] = v;
        accs[k >> 1] = fmaf(v, sA[c], accs[k >> 1]);
        accd[k >> 1] = fmaf(v, sB[c], accd[k >> 1]);
    }
#pragma unroll
    for (int h = 0; h < 4; h++) {
        float vs = accs[h], vd = accd[h];
#pragma unroll
        for (int o = 16; o; o >>= 1) {
            vs += __shfl_down_sync(0xffffffffu, vs, o);
            vd += __shfl_down_sync(0xffffffffu, vd, o);
        }
        if (lane == 0) { g_als1[warp * 4 + h] = vs; g_ald1[warp * 4 + h] = vd; }
    }
}

// ---- conv1 edge attention weights (no atomics) ----
__global__ void k_att1(const int* __restrict__ src, const int* __restrict__ dst,
                       const float* __restrict__ ea, int e, int n) {
    int idx = blockIdx.x * blockDim.x + threadIdx.x;
    if (idx >= e + n) return;
    int s, d; float a;
    if (idx < e) { s = src[idx]; d = dst[idx]; a = ea[idx]; }
    else { s = d = idx - e; a = g_loop_sum[s] / fmaxf(g_loop_cnt[s], 1.f); }
    float4 ls = *reinterpret_cast<const float4*>(&g_als1[s * 4]);
    float4 ld = *reinterpret_cast<const float4*>(&g_ald1[d * 4]);
    float4 w;
    w.x = expf(lrelu(ls.x + ld.x + a * g_ce[0]));
    w.y = expf(lrelu(ls.y + ld.y + a * g_ce[1]));
    w.z = expf(lrelu(ls.z + ld.z + a * g_ce[2]));
    w.w = expf(lrelu(ls.w + ld.w + a * g_ce[3]));
    *reinterpret_cast<float4*>(&g_w1[(size_t)idx * 4]) = w;
}

// ---- conv1 gather-aggregate, 64 threads/node, fused softmax-norm + bias + ELU ----
__global__ void k_gather1(const int* __restrict__ src, const float* __restrict__ b1,
                          int e, int n) {
    int gt = blockIdx.x * blockDim.x + threadIdx.x;
    int node = gt >> 6;
    if (node >= n) return;
    int t = gt & 63, h = t >> 4;
    int beg = g_off[node], end = g_off[node + 1];
    float4 acc = make_float4(0, 0, 0, 0);
    float sw = 0.f;
    for (int i = beg; i < end; i++) {
        int eid = g_adj[i];
        int s = (eid < e) ? src[eid] : node;
        float w = g_w1[(size_t)eid * 4 + h];
        float4 v = *reinterpret_cast<const float4*>(&g_xw1[(size_t)s * 256 + t * 4]);
        acc.x = fmaf(w, v.x, acc.x); acc.y = fmaf(w, v.y, acc.y);
        acc.z = fmaf(w, v.z, acc.z); acc.w = fmaf(w, v.w, acc.w);
        sw += w;
    }
    float inv = 1.f / (sw + 1e-16f);
    float4 bb = *reinterpret_cast<const float4*>(&b1[t * 4]);
    float4 o;
    o.x = eluf(acc.x * inv + bb.x); o.y = eluf(acc.y * inv + bb.y);
    o.z = eluf(acc.z * inv + bb.z); o.w = eluf(acc.w * inv + bb.w);
    *reinterpret_cast<float4*>(&g_h1[(size_t)node * 256 + t * 4]) = o;
}

// ---- xw2 = h1 @ W2 (+ fused al_src2/al_dst2). 64 nodes/block, smem-tiled ----
#define XW2_NODES 64
__global__ void k_xw2(const float* __restrict__ W2, const float* __restrict__ as2,
                      const float* __restrict__ ad2, int n) {
    extern __shared__ float sm[];
    float2* sW = reinterpret_cast<float2*>(sm);          // 64KB: W2 as float2 pairs
    float*  srow = sm + 16384;                           // 64KB: 64 rows x 256
    int t = threadIdx.x;                                 // 256 threads
    {
        const float4* w4 = reinterpret_cast<const float4*>(W2);
        float4* d4 = reinterpret_cast<float4*>(sm);
        for (int i = t; i < 4096; i += 256) d4[i] = w4[i];
    }
    int base = blockIdx.x * XW2_NODES;
    int cnt = min(XW2_NODES, n - base);
    {
        const float4* h4 = reinterpret_cast<const float4*>(g_h1 + (size_t)base * 256);
        float4* r4 = reinterpret_cast<float4*>(srow);
        for (int i = t; i < cnt * 64; i += 256) r4[i] = h4[i];
        for (int i = cnt * 64 + t; i < XW2_NODES * 64; i += 256)
            r4[i] = make_float4(0, 0, 0, 0);
    }
    __syncthreads();
    int warp = t >> 5, l = t & 31;
    int nb = warp * 8;
    float a0[8], a1[8];
#pragma unroll
    for (int j = 0; j < 8; j++) { a0[j] = 0.f; a1[j] = 0.f; }
#pragma unroll 4
    for (int k = 0; k < 256; k++) {
        float2 w = sW[k * 32 + l];
#pragma unroll
        for (int j = 0; j < 8; j++) {
            float hv = srow[(nb + j) * 256 + k];
            a0[j] = fmaf(hv, w.x, a0[j]);
            a1[j] = fmaf(hv, w.y, a1[j]);
        }
    }
    float s0 = as2[2 * l], s1 = as2[2 * l + 1];
    float d0 = ad2[2 * l], d1 = ad2[2 * l + 1];
#pragma unroll
    for (int j = 0; j < 8; j++) {
        int node = base + nb + j;
        bool ok = node < n;
        if (ok) {
            float2 o = make_float2(a0[j], a1[j]);
            *reinterpret_cast<float2*>(&g_xw2[(size_t)node * 64 + 2 * l]) = o;
        }
        float vs = a0[j] * s0 + a1[j] * s1;
        float vd = a0[j] * d0 + a1[j] * d1;
#pragma unroll
        for (int o = 16; o; o >>= 1) {
            vs += __shfl_down_sync(0xffffffffu, vs, o);
            vd += __shfl_down_sync(0xffffffffu, vd, o);
        }
        if (l == 0 && ok) { g_als2[node] = vs; g_ald2[node] = vd; }
    }
}

// ---- conv2 edge attention ----
__global__ void k_att2(const int* __restrict__ src, const int* __restrict__ dst,
                       const float* __restrict__ ea, int e, int n) {
    int idx = blockIdx.x * blockDim.x + threadIdx.x;
    if (idx >= e + n) return;
    int s, d; float a;
    if (idx < e) { s = src[idx]; d = dst[idx]; a = ea[idx]; }
    else { s = d = idx - e; a = g_loop_sum[s] / fmaxf(g_loop_cnt[s], 1.f); }
    float lg = g_als2[s] + g_ald2[d] + a * g_ce[4];
    g_w2[idx] = expf(lrelu(lg));
}

// ---- conv2 gather-aggregate, 16 threads/node ----
__global__ void k_gather2(const int* __restrict__ src, int e, int n) {
    int gt = blockIdx.x * blockDim.x + threadIdx.x;
    int node = gt >> 4;
    if (node >= n) return;
    int t = gt & 15;
    int beg = g_off[node], end = g_off[node + 1];
    float4 acc = make_float4(0, 0, 0, 0);
    float sw = 0.f;
    for (int i = beg; i < end; i++) {
        int eid = g_adj[i];
        int s = (eid < e) ? src[eid] : node;
        float w = g_w2[eid];
        float4 v = *reinterpret_cast<const float4*>(&g_xw2[(size_t)s * 64 + t * 4]);
        acc.x = fmaf(w, v.x, acc.x); acc.y = fmaf(w, v.y, acc.y);
        acc.z = fmaf(w, v.z, acc.z); acc.w = fmaf(w, v.w, acc.w);
        sw += w;
    }
    float inv = 1.f / (sw + 1e-16f);
    acc.x *= inv; acc.y *= inv; acc.z *= inv; acc.w *= inv;
    *reinterpret_cast<float4*>(&g_out2[(size_t)node * 64 + t * 4]) = acc;
}

// ---- cluster pooling of out2 + counts + cf (register partials -> smem -> global) ----
__global__ void k_pool(const float* __restrict__ x, const int* __restrict__ assign, int n) {
    __shared__ float sz[264];
    int t = threadIdx.x;
    sz[t] = 0.f;
    if (t < 8) sz[256 + t] = 0.f;
    __syncthreads();
    int gt0 = blockIdx.x * blockDim.x + t;
    int ch = gt0 & 63;
    float r0 = 0, r1 = 0, r2 = 0, r3 = 0;
    float c0 = 0, c1 = 0, c2 = 0, c3 = 0;
    float f0 = 0, f1 = 0, f2 = 0, f3 = 0;
    int total = n * 64;
    int stride = gridDim.x * blockDim.x;    // multiple of 64 by construction
    for (int idx = gt0; idx < total; idx += stride) {
        int node = idx >> 6;
        int a = assign[node];
        float v = g_out2[idx];
        if (a == 0) r0 += v; else if (a == 1) r1 += v; else if (a == 2) r2 += v; else r3 += v;
        if (ch == 0) {
            float cf = x[node * 7 + 6];
            if (a == 0) { c0 += 1.f; f0 += cf; }
            else if (a == 1) { c1 += 1.f; f1 += cf; }
            else if (a == 2) { c2 += 1.f; f2 += cf; }
            else { c3 += 1.f; f3 += cf; }
        }
    }
    atomicAdd(&sz[0 * 64 + ch], r0);
    atomicAdd(&sz[1 * 64 + ch], r1);
    atomicAdd(&sz[2 * 64 + ch], r2);
    atomicAdd(&sz[3 * 64 + ch], r3);
    if (ch == 0) {
        atomicAdd(&sz[256 + 0], c0); atomicAdd(&sz[256 + 1], c1);
        atomicAdd(&sz[256 + 2], c2); atomicAdd(&sz[256 + 3], c3);
        atomicAdd(&sz[260 + 0], f0); atomicAdd(&sz[260 + 1], f1);
        atomicAdd(&sz[260 + 2], f2); atomicAdd(&sz[260 + 3], f3);
    }
    __syncthreads();
    atomicAdd(&g_pool[t], sz[t]);
    if (t < 8) atomicAdd(&g_pool[256 + t], sz[256 + t]);
}

// ---- final: means + MLP + softmax + write output (1 block, 64 threads) ----
__global__ void k_final(const float* __restrict__ b2, const float* __restrict__ A1,
                        const float* __restrict__ c1, const float* __restrict__ A2,
                        const float* __restrict__ c2, float* __restrict__ out) {
    __shared__ float z[4][64];
    __shared__ float red[64];
    __shared__ float logits[4];
    __shared__ float probs[4];
    int t = threadIdx.x;
    float cf[4];
#pragma unroll
    for (int k = 0; k < 4; k++) {
        float cn = g_pool[256 + k];
        z[k][t] = (cn > 0.f) ? (g_pool[k * 64 + t] / cn + b2[t]) : 0.f;
        cf[k] = (cn > 0.f) ? (g_pool[260 + k] / cn) : 0.f;
    }
    __syncthreads();
    for (int k = 0; k < 4; k++) {
        float acc = c1[t];
        for (int i = 0; i < 64; i++) acc = fmaf(z[k][i], A1[i * 64 + t], acc);
        acc = fmaf(cf[k], A1[64 * 64 + t], acc);
        acc = fmaxf(acc, 0.f) * A2[t];
        red[t] = acc;
        __syncthreads();
        if (t == 0) {
            float s = 0.f;
            for (int i = 0; i < 64; i++) s += red[i];
            logits[k] = s + c2[0];
        }
        __syncthreads();
    }
    if (t == 0) {
        float m = fmaxf(fmaxf(logits[0], logits[1]), fmaxf(logits[2], logits[3]));
        float e0 = expf(logits[0] - m), e1 = expf(logits[1] - m);
        float e2 = expf(logits[2] - m), e3 = expf(logits[3] - m);
        float inv = 1.f / (e0 + e1 + e2 + e3);
        probs[0] = e0 * inv; probs[1] = e1 * inv; probs[2] = e2 * inv; probs[3] = e3 * inv;
    }
    __syncthreads();
    if (t < 4) out[t] = probs[t];
#pragma unroll
    for (int k = 0; k < 4; k++) out[4 + k * 64 + t] = z[k][t];
}

extern "C" void kernel_launch(void* const* d_in, const int* in_sizes, int n_in,
                              void* d_out, int out_size) {
    const float* x    = (const float*)d_in[0];
    const int*   ei   = (const int*)d_in[1];
    const float* ea   = (const float*)d_in[2];
    const int*   assign = (const int*)d_in[3];
    const float* W1   = (const float*)d_in[4];
    const float* as1  = (const float*)d_in[5];
    const float* ad1  = (const float*)d_in[6];
    const float* We1  = (const float*)d_in[7];
    const float* ae1  = (const float*)d_in[8];
    const float* b1   = (const float*)d_in[9];
    const float* W2   = (const float*)d_in[10];
    const float* as2  = (const float*)d_in[11];
    const float* ad2  = (const float*)d_in[12];
    const float* We2  = (const float*)d_in[13];
    const float* ae2  = (const float*)d_in[14];
    const float* b2   = (const float*)d_in[15];
    const float* A1   = (const float*)d_in[16];
    const float* c1   = (const float*)d_in[17];
    const float* A2   = (const float*)d_in[18];
    const float* c2   = (const float*)d_in[19];
    float* out = (float*)d_out;

    int n = in_sizes[0] / 7;
    int e = in_sizes[2];
    const int* src = ei;
    const int* dst = ei + e;
    int tot = e + n;
    int nb = (n + SCAN_CHUNK - 1) / SCAN_CHUNK;

    k_init<<<208, 256>>>(We1, ae1, We2, ae2, n);
    k_degloop<<<(tot + 255) / 256, 256>>>(dst, ea, e, n);
    k_xw1<<<(n + 7) / 8, 256>>>(x, W1, as1, ad1, n);
    k_part<<<nb, 1024>>>(n);
    k_scanb<<<1, 32>>>(nb);
    k_offs<<<nb, 1024>>>(n, tot);
    k_fill<<<(tot + 255) / 256, 256>>>(dst, e, n);
    k_att1<<<(tot + 255) / 256, 256>>>(src, dst, ea, e, n);
    k_gather1<<<(n * 64 + 255) / 256, 256>>>(src, b1, e, n);

    cudaFuncSetAttribute(k_xw2, cudaFuncAttributeMaxDynamicSharedMemorySize, 131072);
    k_xw2<<<(n + XW2_NODES - 1) / XW2_NODES, 256, 131072>>>(W2, as2, ad2, n);

    k_att2<<<(tot + 255) / 256, 256>>>(src, dst, ea, e, n);
    k_gather2<<<(n * 16 + 255) / 256, 256>>>(src, e, n);
    k_pool<<<1184, 256>>>(x, assign, n);
    k_final<<<1, 64>>>(b2, A1, c1, A2, c2, out);
}

// round 3
// speedup vs baseline: 1.6420x; 1.3087x over previous
#include <cuda_runtime.h>
#include <cuda_bf16.h>
#include <math.h>

#define MAXN 50048
#define MAXE 800000
#define MAXT (MAXE + MAXN)
#define SCAN_CHUNK 4096

// ---- scratch (static __device__, no allocations) ----
__device__ __align__(16) __nv_bfloat16 g_xw1b[MAXN * 256];
__device__ __align__(16) float g_als1[MAXN * 4];
__device__ __align__(16) float g_ald1[MAXN * 4];
__device__ float g_loop_sum[MAXN];
__device__ int   g_dcnt[MAXN];
__device__ int   g_off[MAXN + 1];
__device__ int   g_cur[MAXN];
__device__ int   g_adj[MAXT];
__device__ int   g_asrc[MAXT];
__device__ int   g_bsum[64];
__device__ __align__(16) float g_w1[MAXT * 4];
__device__ __align__(16) __nv_bfloat16 g_h1b[MAXN * 256];
__device__ __align__(16) __nv_bfloat16 g_xw2b[MAXN * 64];
__device__ float g_als2[MAXN];
__device__ float g_ald2[MAXN];
__device__ float g_w2[MAXT];
__device__ __align__(16) float g_out2[MAXN * 64];
__device__ float g_ce[5];
__device__ float g_pool[264];   // [0:256) zsum[4][64], [256:260) cnt, [260:264) cf

__device__ __forceinline__ float lrelu(float x) { return x > 0.f ? x : 0.2f * x; }
__device__ __forceinline__ float eluf(float x)  { return x > 0.f ? x : (expf(x) - 1.f); }

// ---- init: zero scratch + compute per-head edge-attention constants ----
__global__ void k_init(const float* __restrict__ We1, const float* __restrict__ ae1,
                       const float* __restrict__ We2, const float* __restrict__ ae2, int n) {
    int gt = blockIdx.x * blockDim.x + threadIdx.x;
    int stride = gridDim.x * blockDim.x;
    for (int i = gt; i < n; i += stride) {
        g_loop_sum[i] = 0.f;
        g_dcnt[i] = 0;
    }
    if (gt < 264) g_pool[gt] = 0.f;
    if (blockIdx.x == 0) {
        __shared__ float s[5];
        int t = threadIdx.x;
        if (t < 5) s[t] = 0.f;
        __syncthreads();
        if (t < 256) atomicAdd(&s[t >> 6], We1[t] * ae1[t]);
        if (t < 64) atomicAdd(&s[4], We2[t] * ae2[t]);
        __syncthreads();
        if (t < 5) g_ce[t] = s[t];
    }
}

// ---- per-dst degree (incl. self loop) + self-loop attr sums ----
__global__ void k_degloop(const int* __restrict__ dst, const float* __restrict__ ea,
                          int e, int n) {
    int idx = blockIdx.x * blockDim.x + threadIdx.x;
    if (idx >= e + n) return;
    int d;
    if (idx < e) {
        d = dst[idx];
        atomicAdd(&g_loop_sum[d], ea[idx]);
    } else {
        d = idx - e;
    }
    atomicAdd(&g_dcnt[d], 1);
}

// ---- device-wide exclusive scan, stage 1: per-block sums (1024 thr, 4096 elems) ----
__global__ void k_part(int n) {
    int t = threadIdx.x;
    int base = blockIdx.x * SCAN_CHUNK + t * 4;
    int s = 0;
#pragma unroll
    for (int i = 0; i < 4; i++) {
        int idx = base + i;
        if (idx < n) s += g_dcnt[idx];
    }
#pragma unroll
    for (int o = 16; o; o >>= 1) s += __shfl_down_sync(0xffffffffu, s, o);
    __shared__ int ws[32];
    if ((t & 31) == 0) ws[t >> 5] = s;
    __syncthreads();
    if (t < 32) {
        int v = ws[t];
#pragma unroll
        for (int o = 16; o; o >>= 1) v += __shfl_down_sync(0xffffffffu, v, o);
        if (t == 0) g_bsum[blockIdx.x] = v;
    }
}

// ---- stage 2: block-local scan (+ inline scan of block sums) -> offsets/cursors ----
__global__ void k_offs(int n, int tot, int nb) {
    int t = threadIdx.x;
    __shared__ int spre[32];
    if (t < 32) {
        int s = (t < nb) ? g_bsum[t] : 0;
        int v = s;
#pragma unroll
        for (int o = 1; o < 32; o <<= 1) {
            int u = __shfl_up_sync(0xffffffffu, v, o);
            if (t >= o) v += u;
        }
        spre[t] = v - s;
    }
    int base = blockIdx.x * SCAN_CHUNK + t * 4;
    int v[4];
    int s = 0;
#pragma unroll
    for (int i = 0; i < 4; i++) {
        int idx = base + i;
        v[i] = (idx < n) ? g_dcnt[idx] : 0;
        s += v[i];
    }
    int lane = t & 31, w = t >> 5;
    int ps = s;
#pragma unroll
    for (int o = 1; o < 32; o <<= 1) {
        int u = __shfl_up_sync(0xffffffffu, ps, o);
        if (lane >= o) ps += u;
    }
    __shared__ int ws[32];
    if (lane == 31) ws[w] = ps;
    __syncthreads();
    if (t < 32) {
        int x = ws[t];
#pragma unroll
        for (int o = 1; o < 32; o <<= 1) {
            int u = __shfl_up_sync(0xffffffffu, x, o);
            if (t >= o) x += u;
        }
        ws[t] = x;
    }
    __syncthreads();
    int excl = ps - s + (w ? ws[w - 1] : 0) + spre[blockIdx.x];
#pragma unroll
    for (int i = 0; i < 4; i++) {
        int idx = base + i;
        if (idx < n) {
            g_off[idx] = excl;
            g_cur[idx] = excl;
            excl += v[i];
        }
    }
    if (blockIdx.x == 0 && t == 0) g_off[n] = tot;
}

// ---- fill adjacency (edges grouped by dst); also stash src per slot ----
__global__ void k_fill(const int* __restrict__ src, const int* __restrict__ dst,
                       int e, int n) {
    int idx = blockIdx.x * blockDim.x + threadIdx.x;
    if (idx >= e + n) return;
    int d, s;
    if (idx < e) { d = dst[idx]; s = src[idx]; }
    else { d = idx - e; s = d; }
    int p = atomicAdd(&g_cur[d], 1);
    g_adj[p] = idx;
    g_asrc[p] = s;
}

// ---- xw1 = x @ W1 (+ fused al_src1 / al_dst1), one warp per node, bf16 store ----
__global__ void k_xw1(const float* __restrict__ x, const float* __restrict__ W1,
                      const float* __restrict__ as1, const float* __restrict__ ad1, int n) {
    __shared__ float sW[7 * 256];
    __shared__ float sA[256];
    __shared__ float sB[256];
    int t = threadIdx.x;
    for (int i = t; i < 7 * 256; i += blockDim.x) sW[i] = W1[i];
    if (t < 256) { sA[t] = as1[t]; sB[t] = ad1[t]; }
    __syncthreads();
    int node = (blockIdx.x * blockDim.x + t) >> 5;
    int lane = t & 31;
    if (node >= n) return;
    float xv[7];
#pragma unroll
    for (int i = 0; i < 7; i++) xv[i] = x[node * 7 + i];
    const float2* sW2 = reinterpret_cast<const float2*>(sW);
    const float2* sA2 = reinterpret_cast<const float2*>(sA);
    const float2* sB2 = reinterpret_cast<const float2*>(sB);
    float accs[4], accd[4];
    __nv_bfloat162* ob = reinterpret_cast<__nv_bfloat162*>(g_xw1b) + (size_t)node * 128;
#pragma unroll
    for (int k = 0; k < 4; k++) {
        int p = k * 32 + lane;                 // float2 index within 128-wide row
        float v0 = 0.f, v1 = 0.f;
#pragma unroll
        for (int i = 0; i < 7; i++) {
            float2 wv = sW2[i * 128 + p];
            v0 = fmaf(xv[i], wv.x, v0);
            v1 = fmaf(xv[i], wv.y, v1);
        }
        float2 av = sA2[p], bv = sB2[p];
        accs[k] = fmaf(v0, av.x, v1 * av.y);
        accd[k] = fmaf(v0, bv.x, v1 * bv.y);
        ob[p] = __floats2bfloat162_rn(v0, v1);
    }
#pragma unroll
    for (int h = 0; h < 4; h++) {
        float vs = accs[h], vd = accd[h];
#pragma unroll
        for (int o = 16; o; o >>= 1) {
            vs += __shfl_down_sync(0xffffffffu, vs, o);
            vd += __shfl_down_sync(0xffffffffu, vd, o);
        }
        if (lane == 0) { g_als1[node * 4 + h] = vs; g_ald1[node * 4 + h] = vd; }
    }
}

// ---- conv1 edge attention weights ----
__global__ void k_att1(const int* __restrict__ src, const int* __restrict__ dst,
                       const float* __restrict__ ea, int e, int n) {
    int idx = blockIdx.x * blockDim.x + threadIdx.x;
    if (idx >= e + n) return;
    int s, d; float a;
    if (idx < e) { s = src[idx]; d = dst[idx]; a = ea[idx]; }
    else {
        s = d = idx - e;
        float cnt = (float)(g_off[s + 1] - g_off[s] - 1);
        a = g_loop_sum[s] / fmaxf(cnt, 1.f);
    }
    float4 ls = *reinterpret_cast<const float4*>(&g_als1[s * 4]);
    float4 ld = *reinterpret_cast<const float4*>(&g_ald1[d * 4]);
    float4 w;
    w.x = expf(lrelu(ls.x + ld.x + a * g_ce[0]));
    w.y = expf(lrelu(ls.y + ld.y + a * g_ce[1]));
    w.z = expf(lrelu(ls.z + ld.z + a * g_ce[2]));
    w.w = expf(lrelu(ls.w + ld.w + a * g_ce[3]));
    *reinterpret_cast<float4*>(&g_w1[(size_t)idx * 4]) = w;
}

// ---- conv1 gather-aggregate, 32 threads/node (8 ch each), bf16 rows ----
__global__ void k_gather1(const float* __restrict__ b1, int e, int n) {
    int gt = blockIdx.x * blockDim.x + threadIdx.x;
    int node = gt >> 5;
    if (node >= n) return;
    int l = gt & 31, h = l >> 3;
    int beg = g_off[node], end = g_off[node + 1];
    float acc0 = 0, acc1 = 0, acc2 = 0, acc3 = 0, acc4 = 0, acc5 = 0, acc6 = 0, acc7 = 0;
    float sw = 0.f;
    for (int i = beg; i < end; i++) {
        int eid = g_adj[i];
        int s = g_asrc[i];
        float w = g_w1[(size_t)eid * 4 + h];
        uint4 raw = *reinterpret_cast<const uint4*>(g_xw1b + (size_t)s * 256 + l * 8);
        float2 p0 = __bfloat1622float2(*reinterpret_cast<__nv_bfloat162*>(&raw.x));
        float2 p1 = __bfloat1622float2(*reinterpret_cast<__nv_bfloat162*>(&raw.y));
        float2 p2 = __bfloat1622float2(*reinterpret_cast<__nv_bfloat162*>(&raw.z));
        float2 p3 = __bfloat1622float2(*reinterpret_cast<__nv_bfloat162*>(&raw.w));
        acc0 = fmaf(w, p0.x, acc0); acc1 = fmaf(w, p0.y, acc1);
        acc2 = fmaf(w, p1.x, acc2); acc3 = fmaf(w, p1.y, acc3);
        acc4 = fmaf(w, p2.x, acc4); acc5 = fmaf(w, p2.y, acc5);
        acc6 = fmaf(w, p3.x, acc6); acc7 = fmaf(w, p3.y, acc7);
        sw += w;
    }
    float inv = 1.f / (sw + 1e-16f);
    const float4* b4 = reinterpret_cast<const float4*>(b1);
    float4 ba = b4[l * 2], bb = b4[l * 2 + 1];
    float o0 = eluf(acc0 * inv + ba.x), o1 = eluf(acc1 * inv + ba.y);
    float o2 = eluf(acc2 * inv + ba.z), o3 = eluf(acc3 * inv + ba.w);
    float o4 = eluf(acc4 * inv + bb.x), o5 = eluf(acc5 * inv + bb.y);
    float o6 = eluf(acc6 * inv + bb.z), o7 = eluf(acc7 * inv + bb.w);
    uint4 outw;
    *reinterpret_cast<__nv_bfloat162*>(&outw.x) = __floats2bfloat162_rn(o0, o1);
    *reinterpret_cast<__nv_bfloat162*>(&outw.y) = __floats2bfloat162_rn(o2, o3);
    *reinterpret_cast<__nv_bfloat162*>(&outw.z) = __floats2bfloat162_rn(o4, o5);
    *reinterpret_cast<__nv_bfloat162*>(&outw.w) = __floats2bfloat162_rn(o6, o7);
    *reinterpret_cast<uint4*>(g_h1b + (size_t)node * 256 + l * 8) = outw;
}

// ---- xw2 = h1 @ W2 (+ fused al_src2/al_dst2). 64 nodes/block, smem-tiled ----
#define XW2_NODES 64
__global__ void k_xw2(const float* __restrict__ W2, const float* __restrict__ as2,
                      const float* __restrict__ ad2, int n) {
    extern __shared__ float sm[];
    float2* sW = reinterpret_cast<float2*>(sm);          // 64KB: W2 as float2 pairs
    float*  srow = sm + 16384;                           // 64KB: 64 rows x 256 fp32
    int t = threadIdx.x;                                 // 256 threads
    {
        const float4* w4 = reinterpret_cast<const float4*>(W2);
        float4* d4 = reinterpret_cast<float4*>(sm);
        for (int i = t; i < 4096; i += 256) d4[i] = w4[i];
    }
    int base = blockIdx.x * XW2_NODES;
    int cnt = min(XW2_NODES, n - base);
    {
        const uint4* h4 = reinterpret_cast<const uint4*>(g_h1b + (size_t)base * 256);
        for (int i = t; i < cnt * 32; i += 256) {
            uint4 raw = h4[i];
            float* dp = srow + i * 8;
            float2 p0 = __bfloat1622float2(*reinterpret_cast<__nv_bfloat162*>(&raw.x));
            float2 p1 = __bfloat1622float2(*reinterpret_cast<__nv_bfloat162*>(&raw.y));
            float2 p2 = __bfloat1622float2(*reinterpret_cast<__nv_bfloat162*>(&raw.z));
            float2 p3 = __bfloat1622float2(*reinterpret_cast<__nv_bfloat162*>(&raw.w));
            dp[0] = p0.x; dp[1] = p0.y; dp[2] = p1.x; dp[3] = p1.y;
            dp[4] = p2.x; dp[5] = p2.y; dp[6] = p3.x; dp[7] = p3.y;
        }
        for (int i = cnt * 32 + t; i < XW2_NODES * 32; i += 256) {
            float4* dp = reinterpret_cast<float4*>(srow + i * 8);
            dp[0] = make_float4(0, 0, 0, 0);
            dp[1] = make_float4(0, 0, 0, 0);
        }
    }
    __syncthreads();
    int warp = t >> 5, l = t & 31;
    int nb = warp * 8;
    float a0[8], a1[8];
#pragma unroll
    for (int j = 0; j < 8; j++) { a0[j] = 0.f; a1[j] = 0.f; }
#pragma unroll 4
    for (int k = 0; k < 256; k++) {
        float2 w = sW[k * 32 + l];
#pragma unroll
        for (int j = 0; j < 8; j++) {
            float hv = srow[(nb + j) * 256 + k];
            a0[j] = fmaf(hv, w.x, a0[j]);
            a1[j] = fmaf(hv, w.y, a1[j]);
        }
    }
    float s0 = as2[2 * l], s1 = as2[2 * l + 1];
    float d0 = ad2[2 * l], d1 = ad2[2 * l + 1];
#pragma unroll
    for (int j = 0; j < 8; j++) {
        int node = base + nb + j;
        bool ok = node < n;
        if (ok) {
            *reinterpret_cast<__nv_bfloat162*>(g_xw2b + (size_t)node * 64 + 2 * l) =
                __floats2bfloat162_rn(a0[j], a1[j]);
        }
        float vs = a0[j] * s0 + a1[j] * s1;
        float vd = a0[j] * d0 + a1[j] * d1;
#pragma unroll
        for (int o = 16; o; o >>= 1) {
            vs += __shfl_down_sync(0xffffffffu, vs, o);
            vd += __shfl_down_sync(0xffffffffu, vd, o);
        }
        if (l == 0 && ok) { g_als2[node] = vs; g_ald2[node] = vd; }
    }
}

// ---- conv2 edge attention ----
__global__ void k_att2(const int* __restrict__ src, const int* __restrict__ dst,
                       const float* __restrict__ ea, int e, int n) {
    int idx = blockIdx.x * blockDim.x + threadIdx.x;
    if (idx >= e + n) return;
    int s, d; float a;
    if (idx < e) { s = src[idx]; d = dst[idx]; a = ea[idx]; }
    else {
        s = d = idx - e;
        float cnt = (float)(g_off[s + 1] - g_off[s] - 1);
        a = g_loop_sum[s] / fmaxf(cnt, 1.f);
    }
    float lg = g_als2[s] + g_ald2[d] + a * g_ce[4];
    g_w2[idx] = expf(lrelu(lg));
}

// ---- conv2 gather-aggregate, 16 threads/node (4 ch each), bf16 rows ----
__global__ void k_gather2(int e, int n) {
    int gt = blockIdx.x * blockDim.x + threadIdx.x;
    int node = gt >> 4;
    if (node >= n) return;
    int t = gt & 15;
    int beg = g_off[node], end = g_off[node + 1];
    float4 acc = make_float4(0, 0, 0, 0);
    float sw = 0.f;
    for (int i = beg; i < end; i++) {
        int eid = g_adj[i];
        int s = g_asrc[i];
        float w = g_w2[eid];
        uint2 raw = *reinterpret_cast<const uint2*>(g_xw2b + (size_t)s * 64 + t * 4);
        float2 p0 = __bfloat1622float2(*reinterpret_cast<__nv_bfloat162*>(&raw.x));
        float2 p1 = __bfloat1622float2(*reinterpret_cast<__nv_bfloat162*>(&raw.y));
        acc.x = fmaf(w, p0.x, acc.x); acc.y = fmaf(w, p0.y, acc.y);
        acc.z = fmaf(w, p1.x, acc.z); acc.w = fmaf(w, p1.y, acc.w);
        sw += w;
    }
    float inv = 1.f / (sw + 1e-16f);
    acc.x *= inv; acc.y *= inv; acc.z *= inv; acc.w *= inv;
    *reinterpret_cast<float4*>(&g_out2[(size_t)node * 64 + t * 4]) = acc;
}

// ---- cluster pooling of out2 + counts + cf (register partials -> smem -> global) ----
__global__ void k_pool(const float* __restrict__ x, const int* __restrict__ assign, int n) {
    __shared__ float sz[264];
    int t = threadIdx.x;
    sz[t] = 0.f;
    if (t < 8) sz[256 + t] = 0.f;
    __syncthreads();
    int gt0 = blockIdx.x * blockDim.x + t;
    int ch = gt0 & 63;
    float r0 = 0, r1 = 0, r2 = 0, r3 = 0;
    float c0 = 0, c1 = 0, c2 = 0, c3 = 0;
    float f0 = 0, f1 = 0, f2 = 0, f3 = 0;
    int total = n * 64;
    int stride = gridDim.x * blockDim.x;    // multiple of 64 by construction
    for (int idx = gt0; idx < total; idx += stride) {
        int node = idx >> 6;
        int a = assign[node];
        float v = g_out2[idx];
        if (a == 0) r0 += v; else if (a == 1) r1 += v; else if (a == 2) r2 += v; else r3 += v;
        if (ch == 0) {
            float cf = x[node * 7 + 6];
            if (a == 0) { c0 += 1.f; f0 += cf; }
            else if (a == 1) { c1 += 1.f; f1 += cf; }
            else if (a == 2) { c2 += 1.f; f2 += cf; }
            else { c3 += 1.f; f3 += cf; }
        }
    }
    atomicAdd(&sz[0 * 64 + ch], r0);
    atomicAdd(&sz[1 * 64 + ch], r1);
    atomicAdd(&sz[2 * 64 + ch], r2);
    atomicAdd(&sz[3 * 64 + ch], r3);
    if (ch == 0) {
        atomicAdd(&sz[256 + 0], c0); atomicAdd(&sz[256 + 1], c1);
        atomicAdd(&sz[256 + 2], c2); atomicAdd(&sz[256 + 3], c3);
        atomicAdd(&sz[260 + 0], f0); atomicAdd(&sz[260 + 1], f1);
        atomicAdd(&sz[260 + 2], f2); atomicAdd(&sz[260 + 3], f3);
    }
    __syncthreads();
    atomicAdd(&g_pool[t], sz[t]);
    if (t < 8) atomicAdd(&g_pool[256 + t], sz[256 + t]);
}

// ---- final: means + MLP + softmax + write output (1 block, 64 threads) ----
__global__ void k_final(const float* __restrict__ b2, const float* __restrict__ A1,
                        const float* __restrict__ c1, const float* __restrict__ A2,
                        const float* __restrict__ c2, float* __restrict__ out) {
    __shared__ float z[4][64];
    __shared__ float red[64];
    __shared__ float logits[4];
    __shared__ float probs[4];
    int t = threadIdx.x;
    float cf[4];
#pragma unroll
    for (int k = 0; k < 4; k++) {
        float cn = g_pool[256 + k];
        z[k][t] = (cn > 0.f) ? (g_pool[k * 64 + t] / cn + b2[t]) : 0.f;
        cf[k] = (cn > 0.f) ? (g_pool[260 + k] / cn) : 0.f;
    }
    __syncthreads();
    for (int k = 0; k < 4; k++) {
        float acc = c1[t];
        for (int i = 0; i < 64; i++) acc = fmaf(z[k][i], A1[i * 64 + t], acc);
        acc = fmaf(cf[k], A1[64 * 64 + t], acc);
        acc = fmaxf(acc, 0.f) * A2[t];
        red[t] = acc;
        __syncthreads();
        if (t == 0) {
            float s = 0.f;
            for (int i = 0; i < 64; i++) s += red[i];
            logits[k] = s + c2[0];
        }
        __syncthreads();
    }
    if (t == 0) {
        float m = fmaxf(fmaxf(logits[0], logits[1]), fmaxf(logits[2], logits[3]));
        float e0 = expf(logits[0] - m), e1 = expf(logits[1] - m);
        float e2 = expf(logits[2] - m), e3 = expf(logits[3] - m);
        float inv = 1.f / (e0 + e1 + e2 + e3);
        probs[0] = e0 * inv; probs[1] = e1 * inv; probs[2] = e2 * inv; probs[3] = e3 * inv;
    }
    __syncthreads();
    if (t < 4) out[t] = probs[t];
#pragma unroll
    for (int k = 0; k < 4; k++) out[4 + k * 64 + t] = z[k][t];
}

extern "C" void kernel_launch(void* const* d_in, const int* in_sizes, int n_in,
                              void* d_out, int out_size) {
    const float* x    = (const float*)d_in[0];
    const int*   ei   = (const int*)d_in[1];
    const float* ea   = (const float*)d_in[2];
    const int*   assign = (const int*)d_in[3];
    const float* W1   = (const float*)d_in[4];
    const float* as1  = (const float*)d_in[5];
    const float* ad1  = (const float*)d_in[6];
    const float* We1  = (const float*)d_in[7];
    const float* ae1  = (const float*)d_in[8];
    const float* b1   = (const float*)d_in[9];
    const float* W2   = (const float*)d_in[10];
    const float* as2  = (const float*)d_in[11];
    const float* ad2  = (const float*)d_in[12];
    const float* We2  = (const float*)d_in[13];
    const float* ae2  = (const float*)d_in[14];
    const float* b2   = (const float*)d_in[15];
    const float* A1   = (const float*)d_in[16];
    const float* c1   = (const float*)d_in[17];
    const float* A2   = (const float*)d_in[18];
    const float* c2   = (const float*)d_in[19];
    float* out = (float*)d_out;

    int n = in_sizes[0] / 7;
    int e = in_sizes[2];
    const int* src = ei;
    const int* dst = ei + e;
    int tot = e + n;
    int nb = (n + SCAN_CHUNK - 1) / SCAN_CHUNK;

    k_init<<<208, 256>>>(We1, ae1, We2, ae2, n);
    k_degloop<<<(tot + 255) / 256, 256>>>(dst, ea, e, n);
    k_xw1<<<(n + 7) / 8, 256>>>(x, W1, as1, ad1, n);
    k_part<<<nb, 1024>>>(n);
    k_offs<<<nb, 1024>>>(n, tot, nb);
    k_fill<<<(tot + 255) / 256, 256>>>(src, dst, e, n);
    k_att1<<<(tot + 255) / 256, 256>>>(src, dst, ea, e, n);
    k_gather1<<<(n * 32 + 255) / 256, 256>>>(b1, e, n);

    cudaFuncSetAttribute(k_xw2, cudaFuncAttributeMaxDynamicSharedMemorySize, 131072);
    k_xw2<<<(n + XW2_NODES - 1) / XW2_NODES, 256, 131072>>>(W2, as2, ad2, n);

    k_att2<<<(tot + 255) / 256, 256>>>(src, dst, ea, e, n);
    k_gather2<<<(n * 16 + 255) / 256, 256>>>(e, n);
    k_pool<<<1184, 256>>>(x, assign, n);
    k_final<<<1, 64>>>(b2, A1, c1, A2, c2, out);
}

// round 4
// speedup vs baseline: 1.6844x; 1.0258x over previous
#include <cuda_runtime.h>
#include <cuda_bf16.h>
#include <math.h>

#define MAXN 50048
#define MAXE 800000
#define MAXT (MAXE + MAXN)
#define SCAN_CHUNK 4096

// ---- scratch (static __device__, no allocations) ----
__device__ __align__(16) __nv_bfloat16 g_xw1b[MAXN * 256];
__device__ __align__(16) float g_als1[MAXN * 4];
__device__ __align__(16) float g_ald1[MAXN * 4];
__device__ float g_loop_sum[MAXN];
__device__ int   g_dcnt[MAXN];
__device__ int   g_off[MAXN + 1];
__device__ int   g_cur[MAXN];
__device__ __align__(8)  int2  g_slot[MAXT];     // (src, ea-bits) per adjacency slot
__device__ int   g_bsum[64];
__device__ __align__(16) float g_w1s[MAXT * 4];  // conv1 attention weights, slot-ordered
__device__ __align__(16) __nv_bfloat16 g_h1b[MAXN * 256];
__device__ __align__(16) __nv_bfloat16 g_xw2b[MAXN * 64];
__device__ float g_als2[MAXN];
__device__ float g_ald2[MAXN];
__device__ __align__(16) float g_out2[MAXN * 64];
__device__ float g_ce[5];
__device__ float g_pool[264];   // [0:256) zsum[4][64], [256:260) cnt, [260:264) cf

__device__ __forceinline__ float lrelu(float x) { return x > 0.f ? x : 0.2f * x; }
__device__ __forceinline__ float eluf(float x)  { return x > 0.f ? x : (expf(x) - 1.f); }

// packed dual-fp32 FMA (B300 f32x2 pipe; PTX-only form)
__device__ __forceinline__ void ffma2(float2& d, const float2 a, const float2 b) {
    unsigned long long aa, bb;
    memcpy(&aa, &a, 8);
    memcpy(&bb, &b, 8);
    unsigned long long& dd = reinterpret_cast<unsigned long long&>(d);
    asm("fma.rn.f32x2 %0, %1, %2, %0;" : "+l"(dd) : "l"(aa), "l"(bb));
}

// ---- init: zero scratch + compute per-head edge-attention constants ----
__global__ void k_init(const float* __restrict__ We1, const float* __restrict__ ae1,
                       const float* __restrict__ We2, const float* __restrict__ ae2, int n) {
    int gt = blockIdx.x * blockDim.x + threadIdx.x;
    int stride = gridDim.x * blockDim.x;
    for (int i = gt; i < n; i += stride) {
        g_loop_sum[i] = 0.f;
        g_dcnt[i] = 0;
    }
    if (gt < 264) g_pool[gt] = 0.f;
    if (blockIdx.x == 0) {
        __shared__ float s[5];
        int t = threadIdx.x;
        if (t < 5) s[t] = 0.f;
        __syncthreads();
        if (t < 256) atomicAdd(&s[t >> 6], We1[t] * ae1[t]);
        if (t < 64) atomicAdd(&s[4], We2[t] * ae2[t]);
        __syncthreads();
        if (t < 5) g_ce[t] = s[t];
    }
}

// ---- per-dst degree (incl. self loop) + self-loop attr sums ----
__global__ void k_degloop(const int* __restrict__ dst, const float* __restrict__ ea,
                          int e, int n) {
    int idx = blockIdx.x * blockDim.x + threadIdx.x;
    if (idx >= e + n) return;
    int d;
    if (idx < e) {
        d = dst[idx];
        atomicAdd(&g_loop_sum[d], ea[idx]);
    } else {
        d = idx - e;
    }
    atomicAdd(&g_dcnt[d], 1);
}

// ---- device-wide exclusive scan, stage 1: per-block sums (1024 thr, 4096 elems) ----
__global__ void k_part(int n) {
    int t = threadIdx.x;
    int base = blockIdx.x * SCAN_CHUNK + t * 4;
    int s = 0;
#pragma unroll
    for (int i = 0; i < 4; i++) {
        int idx = base + i;
        if (idx < n) s += g_dcnt[idx];
    }
#pragma unroll
    for (int o = 16; o; o >>= 1) s += __shfl_down_sync(0xffffffffu, s, o);
    __shared__ int ws[32];
    if ((t & 31) == 0) ws[t >> 5] = s;
    __syncthreads();
    if (t < 32) {
        int v = ws[t];
#pragma unroll
        for (int o = 16; o; o >>= 1) v += __shfl_down_sync(0xffffffffu, v, o);
        if (t == 0) g_bsum[blockIdx.x] = v;
    }
}

// ---- stage 2: block-local scan (+ inline scan of block sums) -> offsets/cursors ----
__global__ void k_offs(int n, int tot, int nb) {
    int t = threadIdx.x;
    __shared__ int spre[32];
    if (t < 32) {
        int s = (t < nb) ? g_bsum[t] : 0;
        int v = s;
#pragma unroll
        for (int o = 1; o < 32; o <<= 1) {
            int u = __shfl_up_sync(0xffffffffu, v, o);
            if (t >= o) v += u;
        }
        spre[t] = v - s;
    }
    int base = blockIdx.x * SCAN_CHUNK + t * 4;
    int v[4];
    int s = 0;
#pragma unroll
    for (int i = 0; i < 4; i++) {
        int idx = base + i;
        v[i] = (idx < n) ? g_dcnt[idx] : 0;
        s += v[i];
    }
    int lane = t & 31, w = t >> 5;
    int ps = s;
#pragma unroll
    for (int o = 1; o < 32; o <<= 1) {
        int u = __shfl_up_sync(0xffffffffu, ps, o);
        if (lane >= o) ps += u;
    }
    __shared__ int ws[32];
    if (lane == 31) ws[w] = ps;
    __syncthreads();
    if (t < 32) {
        int x = ws[t];
#pragma unroll
        for (int o = 1; o < 32; o <<= 1) {
            int u = __shfl_up_sync(0xffffffffu, x, o);
            if (t >= o) x += u;
        }
        ws[t] = x;
    }
    __syncthreads();
    int excl = ps - s + (w ? ws[w - 1] : 0) + spre[blockIdx.x];
#pragma unroll
    for (int i = 0; i < 4; i++) {
        int idx = base + i;
        if (idx < n) {
            g_off[idx] = excl;
            g_cur[idx] = excl;
            excl += v[i];
        }
    }
    if (blockIdx.x == 0 && t == 0) g_off[n] = tot;
}

// ---- xw1 = x @ W1 (+ fused al_src1 / al_dst1), one warp per node, bf16 store ----
__global__ void k_xw1(const float* __restrict__ x, const float* __restrict__ W1,
                      const float* __restrict__ as1, const float* __restrict__ ad1, int n) {
    __shared__ float sW[7 * 256];
    __shared__ float sA[256];
    __shared__ float sB[256];
    int t = threadIdx.x;
    for (int i = t; i < 7 * 256; i += blockDim.x) sW[i] = W1[i];
    if (t < 256) { sA[t] = as1[t]; sB[t] = ad1[t]; }
    __syncthreads();
    int node = (blockIdx.x * blockDim.x + t) >> 5;
    int lane = t & 31;
    if (node >= n) return;
    float xv[7];
#pragma unroll
    for (int i = 0; i < 7; i++) xv[i] = x[node * 7 + i];
    const float2* sW2 = reinterpret_cast<const float2*>(sW);
    const float2* sA2 = reinterpret_cast<const float2*>(sA);
    const float2* sB2 = reinterpret_cast<const float2*>(sB);
    float accs[4], accd[4];
    __nv_bfloat162* ob = reinterpret_cast<__nv_bfloat162*>(g_xw1b) + (size_t)node * 128;
#pragma unroll
    for (int k = 0; k < 4; k++) {
        int p = k * 32 + lane;                 // float2 index within 128-wide row
        float v0 = 0.f, v1 = 0.f;
#pragma unroll
        for (int i = 0; i < 7; i++) {
            float2 wv = sW2[i * 128 + p];
            v0 = fmaf(xv[i], wv.x, v0);
            v1 = fmaf(xv[i], wv.y, v1);
        }
        float2 av = sA2[p], bv = sB2[p];
        accs[k] = fmaf(v0, av.x, v1 * av.y);
        accd[k] = fmaf(v0, bv.x, v1 * bv.y);
        ob[p] = __floats2bfloat162_rn(v0, v1);
    }
#pragma unroll
    for (int h = 0; h < 4; h++) {
        float vs = accs[h], vd = accd[h];
#pragma unroll
        for (int o = 16; o; o >>= 1) {
            vs += __shfl_down_sync(0xffffffffu, vs, o);
            vd += __shfl_down_sync(0xffffffffu, vd, o);
        }
        if (lane == 0) { g_als1[node * 4 + h] = vs; g_ald1[node * 4 + h] = vd; }
    }
}

// ---- fill adjacency + fused conv1 attention: slot gets (src, ea) and w1[4] ----
__global__ void k_fill(const int* __restrict__ src, const int* __restrict__ dst,
                       const float* __restrict__ ea, int e, int n) {
    int idx = blockIdx.x * blockDim.x + threadIdx.x;
    if (idx >= e + n) return;
    int d, s; float a;
    if (idx < e) { d = dst[idx]; s = src[idx]; a = ea[idx]; }
    else {
        d = idx - e; s = d;
        float cnt = (float)(g_dcnt[d] - 1);
        a = g_loop_sum[d] / fmaxf(cnt, 1.f);
    }
    float4 ls = *reinterpret_cast<const float4*>(&g_als1[s * 4]);
    float4 ld = *reinterpret_cast<const float4*>(&g_ald1[d * 4]);
    float4 w;
    w.x = expf(lrelu(ls.x + ld.x + a * g_ce[0]));
    w.y = expf(lrelu(ls.y + ld.y + a * g_ce[1]));
    w.z = expf(lrelu(ls.z + ld.z + a * g_ce[2]));
    w.w = expf(lrelu(ls.w + ld.w + a * g_ce[3]));
    int p = atomicAdd(&g_cur[d], 1);
    g_slot[p] = make_int2(s, __float_as_int(a));
    *reinterpret_cast<float4*>(&g_w1s[(size_t)p * 4]) = w;
}

// ---- conv1 gather-aggregate, 32 threads/node (8 ch each), bf16 rows ----
__global__ void k_gather1(const float* __restrict__ b1, int n) {
    int gt = blockIdx.x * blockDim.x + threadIdx.x;
    int node = gt >> 5;
    if (node >= n) return;
    int l = gt & 31, h = l >> 3;
    int beg = g_off[node], end = g_off[node + 1];
    float acc0 = 0, acc1 = 0, acc2 = 0, acc3 = 0, acc4 = 0, acc5 = 0, acc6 = 0, acc7 = 0;
    float sw = 0.f;
    for (int i = beg; i < end; i++) {
        int s = g_slot[i].x;
        float w = g_w1s[(size_t)i * 4 + h];
        uint4 raw = *reinterpret_cast<const uint4*>(g_xw1b + (size_t)s * 256 + l * 8);
        float2 p0 = __bfloat1622float2(*reinterpret_cast<__nv_bfloat162*>(&raw.x));
        float2 p1 = __bfloat1622float2(*reinterpret_cast<__nv_bfloat162*>(&raw.y));
        float2 p2 = __bfloat1622float2(*reinterpret_cast<__nv_bfloat162*>(&raw.z));
        float2 p3 = __bfloat1622float2(*reinterpret_cast<__nv_bfloat162*>(&raw.w));
        acc0 = fmaf(w, p0.x, acc0); acc1 = fmaf(w, p0.y, acc1);
        acc2 = fmaf(w, p1.x, acc2); acc3 = fmaf(w, p1.y, acc3);
        acc4 = fmaf(w, p2.x, acc4); acc5 = fmaf(w, p2.y, acc5);
        acc6 = fmaf(w, p3.x, acc6); acc7 = fmaf(w, p3.y, acc7);
        sw += w;
    }
    float inv = 1.f / (sw + 1e-16f);
    const float4* b4 = reinterpret_cast<const float4*>(b1);
    float4 ba = b4[l * 2], bb = b4[l * 2 + 1];
    float o0 = eluf(acc0 * inv + ba.x), o1 = eluf(acc1 * inv + ba.y);
    float o2 = eluf(acc2 * inv + ba.z), o3 = eluf(acc3 * inv + ba.w);
    float o4 = eluf(acc4 * inv + bb.x), o5 = eluf(acc5 * inv + bb.y);
    float o6 = eluf(acc6 * inv + bb.z), o7 = eluf(acc7 * inv + bb.w);
    uint4 outw;
    *reinterpret_cast<__nv_bfloat162*>(&outw.x) = __floats2bfloat162_rn(o0, o1);
    *reinterpret_cast<__nv_bfloat162*>(&outw.y) = __floats2bfloat162_rn(o2, o3);
    *reinterpret_cast<__nv_bfloat162*>(&outw.z) = __floats2bfloat162_rn(o4, o5);
    *reinterpret_cast<__nv_bfloat162*>(&outw.w) = __floats2bfloat162_rn(o6, o7);
    *reinterpret_cast<uint4*>(g_h1b + (size_t)node * 256 + l * 8) = outw;
}

// ---- xw2 = h1 @ W2 via packed f32x2 FMA. 64 nodes/block ----
#define XW2_NODES 64
__global__ void k_xw2(const float* __restrict__ W2, const float* __restrict__ as2,
                      const float* __restrict__ ad2, int n) {
    extern __shared__ float sm[];
    float* sWx = sm;                 // 32KB: [kq*128 + 4l + c] = W2[(4kq+c)*64 + 2l]
    float* sWy = sm + 8192;          // 32KB: same, col 2l+1
    float* srow = sm + 16384;        // 64KB: 64 rows x 256 fp32
    int t = threadIdx.x;             // 256 threads
    int l = t & 31;
    {
        const float2* w2v = reinterpret_cast<const float2*>(W2);
        for (int k = t >> 5; k < 256; k += 8) {
            float2 w = w2v[k * 32 + l];          // (W2[k][2l], W2[k][2l+1]) coalesced
            int a = (k >> 2) * 128 + l * 4 + (k & 3);
            sWx[a] = w.x;
            sWy[a] = w.y;
        }
    }
    int base = blockIdx.x * XW2_NODES;
    int cnt = min(XW2_NODES, n - base);
    {
        const uint4* h4 = reinterpret_cast<const uint4*>(g_h1b + (size_t)base * 256);
        for (int i = t; i < cnt * 32; i += 256) {
            uint4 raw = h4[i];
            float* dp = srow + i * 8;
            float2 p0 = __bfloat1622float2(*reinterpret_cast<__nv_bfloat162*>(&raw.x));
            float2 p1 = __bfloat1622float2(*reinterpret_cast<__nv_bfloat162*>(&raw.y));
            float2 p2 = __bfloat1622float2(*reinterpret_cast<__nv_bfloat162*>(&raw.z));
            float2 p3 = __bfloat1622float2(*reinterpret_cast<__nv_bfloat162*>(&raw.w));
            dp[0] = p0.x; dp[1] = p0.y; dp[2] = p1.x; dp[3] = p1.y;
            dp[4] = p2.x; dp[5] = p2.y; dp[6] = p3.x; dp[7] = p3.y;
        }
        for (int i = cnt * 32 + t; i < XW2_NODES * 32; i += 256) {
            float4* dp = reinterpret_cast<float4*>(srow + i * 8);
            dp[0] = make_float4(0, 0, 0, 0);
            dp[1] = make_float4(0, 0, 0, 0);
        }
    }
    __syncthreads();
    int warp = t >> 5;
    int nb = warp * 8;
    const float4* wx4 = reinterpret_cast<const float4*>(sWx);
    const float4* wy4 = reinterpret_cast<const float4*>(sWy);
    const float4* sr4 = reinterpret_cast<const float4*>(srow);
    float2 A0[8], A1[8];
#pragma unroll
    for (int j = 0; j < 8; j++) { A0[j] = make_float2(0, 0); A1[j] = make_float2(0, 0); }
#pragma unroll 2
    for (int kq = 0; kq < 64; kq++) {
        float4 wx = wx4[kq * 32 + l];
        float4 wy = wy4[kq * 32 + l];
        float2 wx01 = make_float2(wx.x, wx.y), wx23 = make_float2(wx.z, wx.w);
        float2 wy01 = make_float2(wy.x, wy.y), wy23 = make_float2(wy.z, wy.w);
#pragma unroll
        for (int j = 0; j < 8; j++) {
            float4 h = sr4[(nb + j) * 64 + kq];
            float2 h01 = make_float2(h.x, h.y), h23 = make_float2(h.z, h.w);
            ffma2(A0[j], h01, wx01);
            ffma2(A0[j], h23, wx23);
            ffma2(A1[j], h01, wy01);
            ffma2(A1[j], h23, wy23);
        }
    }
    float s0 = as2[2 * l], s1 = as2[2 * l + 1];
    float d0 = ad2[2 * l], d1 = ad2[2 * l + 1];
#pragma unroll
    for (int j = 0; j < 8; j++) {
        float a0 = A0[j].x + A0[j].y;
        float a1 = A1[j].x + A1[j].y;
        int node = base + nb + j;
        bool ok = node < n;
        if (ok) {
            *reinterpret_cast<__nv_bfloat162*>(g_xw2b + (size_t)node * 64 + 2 * l) =
                __floats2bfloat162_rn(a0, a1);
        }
        float vs = a0 * s0 + a1 * s1;
        float vd = a0 * d0 + a1 * d1;
#pragma unroll
        for (int o = 16; o; o >>= 1) {
            vs += __shfl_down_sync(0xffffffffu, vs, o);
            vd += __shfl_down_sync(0xffffffffu, vd, o);
        }
        if (l == 0 && ok) { g_als2[node] = vs; g_ald2[node] = vd; }
    }
}

// ---- conv2 gather-aggregate with fused attention, 16 threads/node ----
__global__ void k_gather2(int n) {
    int gt = blockIdx.x * blockDim.x + threadIdx.x;
    int node = gt >> 4;
    if (node >= n) return;
    int t = gt & 15;
    int beg = g_off[node], end = g_off[node + 1];
    float aldv = g_ald2[node];
    float ce4 = g_ce[4];
    float4 acc = make_float4(0, 0, 0, 0);
    float sw = 0.f;
    for (int i = beg; i < end; i++) {
        int2 sd = g_slot[i];
        int s = sd.x;
        float a = __int_as_float(sd.y);
        float w = expf(lrelu(g_als2[s] + aldv + a * ce4));
        uint2 raw = *reinterpret_cast<const uint2*>(g_xw2b + (size_t)s * 64 + t * 4);
        float2 p0 = __bfloat1622float2(*reinterpret_cast<__nv_bfloat162*>(&raw.x));
        float2 p1 = __bfloat1622float2(*reinterpret_cast<__nv_bfloat162*>(&raw.y));
        acc.x = fmaf(w, p0.x, acc.x); acc.y = fmaf(w, p0.y, acc.y);
        acc.z = fmaf(w, p1.x, acc.z); acc.w = fmaf(w, p1.y, acc.w);
        sw += w;
    }
    float inv = 1.f / (sw + 1e-16f);
    acc.x *= inv; acc.y *= inv; acc.z *= inv; acc.w *= inv;
    *reinterpret_cast<float4*>(&g_out2[(size_t)node * 64 + t * 4]) = acc;
}

// ---- cluster pooling of out2 + counts + cf (register partials -> smem -> global) ----
__global__ void k_pool(const float* __restrict__ x, const int* __restrict__ assign, int n) {
    __shared__ float sz[264];
    int t = threadIdx.x;
    sz[t] = 0.f;
    if (t < 8) sz[256 + t] = 0.f;
    __syncthreads();
    int gt0 = blockIdx.x * blockDim.x + t;
    int ch = gt0 & 63;
    float r0 = 0, r1 = 0, r2 = 0, r3 = 0;
    float c0 = 0, c1 = 0, c2 = 0, c3 = 0;
    float f0 = 0, f1 = 0, f2 = 0, f3 = 0;
    int total = n * 64;
    int stride = gridDim.x * blockDim.x;    // multiple of 64 by construction
    for (int idx = gt0; idx < total; idx += stride) {
        int node = idx >> 6;
        int a = assign[node];
        float v = g_out2[idx];
        if (a == 0) r0 += v; else if (a == 1) r1 += v; else if (a == 2) r2 += v; else r3 += v;
        if (ch == 0) {
            float cf = x[node * 7 + 6];
            if (a == 0) { c0 += 1.f; f0 += cf; }
            else if (a == 1) { c1 += 1.f; f1 += cf; }
            else if (a == 2) { c2 += 1.f; f2 += cf; }
            else { c3 += 1.f; f3 += cf; }
        }
    }
    atomicAdd(&sz[0 * 64 + ch], r0);
    atomicAdd(&sz[1 * 64 + ch], r1);
    atomicAdd(&sz[2 * 64 + ch], r2);
    atomicAdd(&sz[3 * 64 + ch], r3);
    if (ch == 0) {
        atomicAdd(&sz[256 + 0], c0); atomicAdd(&sz[256 + 1], c1);
        atomicAdd(&sz[256 + 2], c2); atomicAdd(&sz[256 + 3], c3);
        atomicAdd(&sz[260 + 0], f0); atomicAdd(&sz[260 + 1], f1);
        atomicAdd(&sz[260 + 2], f2); atomicAdd(&sz[260 + 3], f3);
    }
    __syncthreads();
    atomicAdd(&g_pool[t], sz[t]);
    if (t < 8) atomicAdd(&g_pool[256 + t], sz[256 + t]);
}

// ---- final: means + MLP + softmax + write output (1 block, 64 threads) ----
__global__ void k_final(const float* __restrict__ b2, const float* __restrict__ A1,
                        const float* __restrict__ c1, const float* __restrict__ A2,
                        const float* __restrict__ c2, float* __restrict__ out) {
    __shared__ float z[4][64];
    __shared__ float red[64];
    __shared__ float logits[4];
    __shared__ float probs[4];
    int t = threadIdx.x;
    float cf[4];
#pragma unroll
    for (int k = 0; k < 4; k++) {
        float cn = g_pool[256 + k];
        z[k][t] = (cn > 0.f) ? (g_pool[k * 64 + t] / cn + b2[t]) : 0.f;
        cf[k] = (cn > 0.f) ? (g_pool[260 + k] / cn) : 0.f;
    }
    __syncthreads();
    for (int k = 0; k < 4; k++) {
        float acc = c1[t];
        for (int i = 0; i < 64; i++) acc = fmaf(z[k][i], A1[i * 64 + t], acc);
        acc = fmaf(cf[k], A1[64 * 64 + t], acc);
        acc = fmaxf(acc, 0.f) * A2[t];
        red[t] = acc;
        __syncthreads();
        if (t == 0) {
            float s = 0.f;
            for (int i = 0; i < 64; i++) s += red[i];
            logits[k] = s + c2[0];
        }
        __syncthreads();
    }
    if (t == 0) {
        float m = fmaxf(fmaxf(logits[0], logits[1]), fmaxf(logits[2], logits[3]));
        float e0 = expf(logits[0] - m), e1 = expf(logits[1] - m);
        float e2 = expf(logits[2] - m), e3 = expf(logits[3] - m);
        float inv = 1.f / (e0 + e1 + e2 + e3);
        probs[0] = e0 * inv; probs[1] = e1 * inv; probs[2] = e2 * inv; probs[3] = e3 * inv;
    }
    __syncthreads();
    if (t < 4) out[t] = probs[t];
#pragma unroll
    for (int k = 0; k < 4; k++) out[4 + k * 64 + t] = z[k][t];
}

extern "C" void kernel_launch(void* const* d_in, const int* in_sizes, int n_in,
                              void* d_out, int out_size) {
    const float* x    = (const float*)d_in[0];
    const int*   ei   = (const int*)d_in[1];
    const float* ea   = (const float*)d_in[2];
    const int*   assign = (const int*)d_in[3];
    const float* W1   = (const float*)d_in[4];
    const float* as1  = (const float*)d_in[5];
    const float* ad1  = (const float*)d_in[6];
    const float* We1  = (const float*)d_in[7];
    const float* ae1  = (const float*)d_in[8];
    const float* b1   = (const float*)d_in[9];
    const float* W2   = (const float*)d_in[10];
    const float* as2  = (const float*)d_in[11];
    const float* ad2  = (const float*)d_in[12];
    const float* We2  = (const float*)d_in[13];
    const float* ae2  = (const float*)d_in[14];
    const float* b2   = (const float*)d_in[15];
    const float* A1   = (const float*)d_in[16];
    const float* c1   = (const float*)d_in[17];
    const float* A2   = (const float*)d_in[18];
    const float* c2   = (const float*)d_in[19];
    float* out = (float*)d_out;

    int n = in_sizes[0] / 7;
    int e = in_sizes[2];
    const int* src = ei;
    const int* dst = ei + e;
    int tot = e + n;
    int nb = (n + SCAN_CHUNK - 1) / SCAN_CHUNK;

    k_init<<<208, 256>>>(We1, ae1, We2, ae2, n);
    k_degloop<<<(tot + 255) / 256, 256>>>(dst, ea, e, n);
    k_xw1<<<(n + 7) / 8, 256>>>(x, W1, as1, ad1, n);
    k_part<<<nb, 1024>>>(n);
    k_offs<<<nb, 1024>>>(n, tot, nb);
    k_fill<<<(tot + 255) / 256, 256>>>(src, dst, ea, e, n);
    k_gather1<<<(n * 32 + 255) / 256, 256>>>(b1, n);

    cudaFuncSetAttribute(k_xw2, cudaFuncAttributeMaxDynamicSharedMemorySize, 131072);
    k_xw2<<<(n + XW2_NODES - 1) / XW2_NODES, 256, 131072>>>(W2, as2, ad2, n);

    k_gather2<<<(n * 16 + 255) / 256, 256>>>(n);
    k_pool<<<1184, 256>>>(x, assign, n);
    k_final<<<1, 64>>>(b2, A1, c1, A2, c2, out);
}

// round 6
// speedup vs baseline: 1.7290x; 1.0265x over previous
#include <cuda_runtime.h>
#include <cuda_bf16.h>
#include <cuda_fp8.h>
#include <math.h>

#define MAXN 50048
#define MAXE 800000
#define MAXT (MAXE + MAXN)
#define SCAN_CHUNK 4096

// ---- scratch (static __device__, no allocations) ----
__device__ __align__(16) unsigned char g_xw1f8[MAXN * 256];
__device__ __align__(16) float g_als1[MAXN * 4];
__device__ __align__(16) float g_ald1[MAXN * 4];
__device__ float g_loop_sum[MAXN];
__device__ int   g_dcnt[MAXN];
__device__ int   g_off[MAXN + 1];
__device__ int   g_cur[MAXN];
__device__ __align__(8)  int2  g_slot[MAXT];     // (src, ea-bits) per adjacency slot
__device__ int   g_bsum[64];
__device__ __align__(16) __nv_bfloat16 g_h1b[MAXN * 256];
__device__ __align__(16) __nv_bfloat16 g_xw2b[MAXN * 64];
__device__ float g_als2[MAXN];
__device__ float g_ald2[MAXN];
__device__ __align__(16) float g_out2[MAXN * 64];
__device__ float g_ce[5];
__device__ float g_pool[264];   // [0:256) zsum[4][64], [256:260) cnt, [260:264) cf

__device__ __forceinline__ float lrelu(float x) { return x > 0.f ? x : 0.2f * x; }
__device__ __forceinline__ float eluf(float x)  { return x > 0.f ? x : (expf(x) - 1.f); }

__device__ __forceinline__ float2 f8x2tof2(unsigned short v) {
    __half2_raw hr = __nv_cvt_fp8x2_to_halfraw2((__nv_fp8x2_storage_t)v, __NV_E4M3);
    return __half22float2(*reinterpret_cast<__half2*>(&hr));
}
__device__ __forceinline__ unsigned short f2tof8x2(float a, float b) {
    return (unsigned short)__nv_cvt_float2_to_fp8x2(make_float2(a, b),
                                                    __NV_SATFINITE, __NV_E4M3);
}

// packed dual-fp32 FMA (B300 f32x2 pipe; PTX-only form)
__device__ __forceinline__ void ffma2(float2& d, const float2 a, const float2 b) {
    unsigned long long aa, bb;
    memcpy(&aa, &a, 8);
    memcpy(&bb, &b, 8);
    unsigned long long& dd = reinterpret_cast<unsigned long long&>(d);
    asm("fma.rn.f32x2 %0, %1, %2, %0;" : "+l"(dd) : "l"(aa), "l"(bb));
}

// ---- init: zero scratch + compute per-head edge-attention constants ----
__global__ void k_init(const float* __restrict__ We1, const float* __restrict__ ae1,
                       const float* __restrict__ We2, const float* __restrict__ ae2, int n) {
    int gt = blockIdx.x * blockDim.x + threadIdx.x;
    int stride = gridDim.x * blockDim.x;
    for (int i = gt; i < n; i += stride) {
        g_loop_sum[i] = 0.f;
        g_dcnt[i] = 0;
    }
    if (gt < 264) g_pool[gt] = 0.f;
    if (blockIdx.x == 0) {
        __shared__ float s[5];
        int t = threadIdx.x;
        if (t < 5) s[t] = 0.f;
        __syncthreads();
        if (t < 256) atomicAdd(&s[t >> 6], We1[t] * ae1[t]);
        if (t < 64) atomicAdd(&s[4], We2[t] * ae2[t]);
        __syncthreads();
        if (t < 5) g_ce[t] = s[t];
    }
}

// ---- per-dst degree (incl. self loop) + self-loop attr sums ----
__global__ void k_degloop(const int* __restrict__ dst, const float* __restrict__ ea,
                          int e, int n) {
    int idx = blockIdx.x * blockDim.x + threadIdx.x;
    if (idx >= e + n) return;
    int d;
    if (idx < e) {
        d = dst[idx];
        atomicAdd(&g_loop_sum[d], ea[idx]);
    } else {
        d = idx - e;
    }
    atomicAdd(&g_dcnt[d], 1);
}

// ---- device-wide exclusive scan, stage 1: per-block sums (1024 thr, 4096 elems) ----
__global__ void k_part(int n) {
    int t = threadIdx.x;
    int base = blockIdx.x * SCAN_CHUNK + t * 4;
    int s = 0;
#pragma unroll
    for (int i = 0; i < 4; i++) {
        int idx = base + i;
        if (idx < n) s += g_dcnt[idx];
    }
#pragma unroll
    for (int o = 16; o; o >>= 1) s += __shfl_down_sync(0xffffffffu, s, o);
    __shared__ int ws[32];
    if ((t & 31) == 0) ws[t >> 5] = s;
    __syncthreads();
    if (t < 32) {
        int v = ws[t];
#pragma unroll
        for (int o = 16; o; o >>= 1) v += __shfl_down_sync(0xffffffffu, v, o);
        if (t == 0) g_bsum[blockIdx.x] = v;
    }
}

// ---- stage 2: block-local scan (+ inline scan of block sums) -> offsets/cursors ----
__global__ void k_offs(int n, int tot, int nb) {
    int t = threadIdx.x;
    __shared__ int spre[32];
    if (t < 32) {
        int s = (t < nb) ? g_bsum[t] : 0;
        int v = s;
#pragma unroll
        for (int o = 1; o < 32; o <<= 1) {
            int u = __shfl_up_sync(0xffffffffu, v, o);
            if (t >= o) v += u;
        }
        spre[t] = v - s;
    }
    int base = blockIdx.x * SCAN_CHUNK + t * 4;
    int v[4];
    int s = 0;
#pragma unroll
    for (int i = 0; i < 4; i++) {
        int idx = base + i;
        v[i] = (idx < n) ? g_dcnt[idx] : 0;
        s += v[i];
    }
    int lane = t & 31, w = t >> 5;
    int ps = s;
#pragma unroll
    for (int o = 1; o < 32; o <<= 1) {
        int u = __shfl_up_sync(0xffffffffu, ps, o);
        if (lane >= o) ps += u;
    }
    __shared__ int ws[32];
    if (lane == 31) ws[w] = ps;
    __syncthreads();
    if (t < 32) {
        int x = ws[t];
#pragma unroll
        for (int o = 1; o < 32; o <<= 1) {
            int u = __shfl_up_sync(0xffffffffu, x, o);
            if (t >= o) x += u;
        }
        ws[t] = x;
    }
    __syncthreads();
    int excl = ps - s + (w ? ws[w - 1] : 0) + spre[blockIdx.x];
#pragma unroll
    for (int i = 0; i < 4; i++) {
        int idx = base + i;
        if (idx < n) {
            g_off[idx] = excl;
            g_cur[idx] = excl;
            excl += v[i];
        }
    }
    if (blockIdx.x == 0 && t == 0) g_off[n] = tot;
}

// ---- xw1 = x @ W1 (+ fused al_src1 / al_dst1), one warp per node, fp8 store ----
__global__ void k_xw1(const float* __restrict__ x, const float* __restrict__ W1,
                      const float* __restrict__ as1, const float* __restrict__ ad1, int n) {
    __shared__ float sW[7 * 256];
    __shared__ float sA[256];
    __shared__ float sB[256];
    int t = threadIdx.x;
    for (int i = t; i < 7 * 256; i += blockDim.x) sW[i] = W1[i];
    if (t < 256) { sA[t] = as1[t]; sB[t] = ad1[t]; }
    __syncthreads();
    int node = (blockIdx.x * blockDim.x + t) >> 5;
    int lane = t & 31;
    if (node >= n) return;
    float xv[7];
#pragma unroll
    for (int i = 0; i < 7; i++) xv[i] = x[node * 7 + i];
    const float2* sW2 = reinterpret_cast<const float2*>(sW);
    const float2* sA2 = reinterpret_cast<const float2*>(sA);
    const float2* sB2 = reinterpret_cast<const float2*>(sB);
    float accs[4], accd[4];
    unsigned short* ob = reinterpret_cast<unsigned short*>(g_xw1f8 + (size_t)node * 256);
#pragma unroll
    for (int k = 0; k < 4; k++) {
        int p = k * 32 + lane;                 // pair index within 128-wide row
        float v0 = 0.f, v1 = 0.f;
#pragma unroll
        for (int i = 0; i < 7; i++) {
            float2 wv = sW2[i * 128 + p];
            v0 = fmaf(xv[i], wv.x, v0);
            v1 = fmaf(xv[i], wv.y, v1);
        }
        float2 av = sA2[p], bv = sB2[p];
        accs[k] = fmaf(v0, av.x, v1 * av.y);
        accd[k] = fmaf(v0, bv.x, v1 * bv.y);
        ob[p] = f2tof8x2(v0, v1);
    }
#pragma unroll
    for (int h = 0; h < 4; h++) {
        float vs = accs[h], vd = accd[h];
#pragma unroll
        for (int o = 16; o; o >>= 1) {
            vs += __shfl_down_sync(0xffffffffu, vs, o);
            vd += __shfl_down_sync(0xffffffffu, vd, o);
        }
        if (lane == 0) { g_als1[node * 4 + h] = vs; g_ald1[node * 4 + h] = vd; }
    }
}

// ---- fill adjacency: slot gets (src, ea-bits); slim, no attention math ----
__global__ void k_fill(const int* __restrict__ src, const int* __restrict__ dst,
                       const float* __restrict__ ea, int e, int n) {
    int idx = blockIdx.x * blockDim.x + threadIdx.x;
    if (idx >= e + n) return;
    int d, s; float a;
    if (idx < e) { d = dst[idx]; s = src[idx]; a = ea[idx]; }
    else {
        d = idx - e; s = d;
        float cnt = (float)(g_dcnt[d] - 1);
        a = g_loop_sum[d] / fmaxf(cnt, 1.f);
    }
    int p = atomicAdd(&g_cur[d], 1);
    g_slot[p] = make_int2(s, __float_as_int(a));
}

// ---- conv1 gather-aggregate, 32 thr/node, fp8 rows, inline attention ----
__global__ void k_gather1(const float* __restrict__ b1, int n) {
    int gt = blockIdx.x * blockDim.x + threadIdx.x;
    int node = gt >> 5;
    if (node >= n) return;
    int l = gt & 31, h = l >> 3;
    int beg = g_off[node], end = g_off[node + 1];
    float ald_h = g_ald1[node * 4 + h];
    float ce_h = g_ce[h];
    float acc0 = 0, acc1 = 0, acc2 = 0, acc3 = 0, acc4 = 0, acc5 = 0, acc6 = 0, acc7 = 0;
    float sw = 0.f;
    for (int i = beg; i < end; i++) {
        int2 sd = g_slot[i];
        int s = sd.x;
        float a = __int_as_float(sd.y);
        float lg = g_als1[s * 4 + h] + ald_h + a * ce_h;
        float w = __expf(lrelu(lg));
        uint2 raw = *reinterpret_cast<const uint2*>(g_xw1f8 + (size_t)s * 256 + l * 8);
        float2 p0 = f8x2tof2((unsigned short)(raw.x & 0xffffu));
        float2 p1 = f8x2tof2((unsigned short)(raw.x >> 16));
        float2 p2 = f8x2tof2((unsigned short)(raw.y & 0xffffu));
        float2 p3 = f8x2tof2((unsigned short)(raw.y >> 16));
        acc0 = fmaf(w, p0.x, acc0); acc1 = fmaf(w, p0.y, acc1);
        acc2 = fmaf(w, p1.x, acc2); acc3 = fmaf(w, p1.y, acc3);
        acc4 = fmaf(w, p2.x, acc4); acc5 = fmaf(w, p2.y, acc5);
        acc6 = fmaf(w, p3.x, acc6); acc7 = fmaf(w, p3.y, acc7);
        sw += w;
    }
    float inv = 1.f / (sw + 1e-16f);
    const float4* b4 = reinterpret_cast<const float4*>(b1);
    float4 ba = b4[l * 2], bb = b4[l * 2 + 1];
    float o0 = eluf(acc0 * inv + ba.x), o1 = eluf(acc1 * inv + ba.y);
    float o2 = eluf(acc2 * inv + ba.z), o3 = eluf(acc3 * inv + ba.w);
    float o4 = eluf(acc4 * inv + bb.x), o5 = eluf(acc5 * inv + bb.y);
    float o6 = eluf(acc6 * inv + bb.z), o7 = eluf(acc7 * inv + bb.w);
    uint4 outw;
    *reinterpret_cast<__nv_bfloat162*>(&outw.x) = __floats2bfloat162_rn(o0, o1);
    *reinterpret_cast<__nv_bfloat162*>(&outw.y) = __floats2bfloat162_rn(o2, o3);
    *reinterpret_cast<__nv_bfloat162*>(&outw.z) = __floats2bfloat162_rn(o4, o5);
    *reinterpret_cast<__nv_bfloat162*>(&outw.w) = __floats2bfloat162_rn(o6, o7);
    *reinterpret_cast<uint4*>(g_h1b + (size_t)node * 256 + l * 8) = outw;
}

// ---- xw2 = h1 @ W2 via packed f32x2 FMA. 64 nodes/block, bf16 store ----
#define XW2_NODES 64
__global__ void k_xw2(const float* __restrict__ W2, const float* __restrict__ as2,
                      const float* __restrict__ ad2, int n) {
    extern __shared__ float sm[];
    float* sWx = sm;                 // 32KB: [kq*128 + 4l + c] = W2[(4kq+c)*64 + 2l]
    float* sWy = sm + 8192;          // 32KB: same, col 2l+1
    float* srow = sm + 16384;        // 64KB: 64 rows x 256 fp32
    int t = threadIdx.x;             // 256 threads
    int l = t & 31;
    {
        const float2* w2v = reinterpret_cast<const float2*>(W2);
        for (int k = t >> 5; k < 256; k += 8) {
            float2 w = w2v[k * 32 + l];          // (W2[k][2l], W2[k][2l+1]) coalesced
            int a = (k >> 2) * 128 + l * 4 + (k & 3);
            sWx[a] = w.x;
            sWy[a] = w.y;
        }
    }
    int base = blockIdx.x * XW2_NODES;
    int cnt = min(XW2_NODES, n - base);
    {
        const uint4* h4 = reinterpret_cast<const uint4*>(g_h1b + (size_t)base * 256);
        for (int i = t; i < cnt * 32; i += 256) {
            uint4 raw = h4[i];
            float* dp = srow + i * 8;
            float2 p0 = __bfloat1622float2(*reinterpret_cast<__nv_bfloat162*>(&raw.x));
            float2 p1 = __bfloat1622float2(*reinterpret_cast<__nv_bfloat162*>(&raw.y));
            float2 p2 = __bfloat1622float2(*reinterpret_cast<__nv_bfloat162*>(&raw.z));
            float2 p3 = __bfloat1622float2(*reinterpret_cast<__nv_bfloat162*>(&raw.w));
            dp[0] = p0.x; dp[1] = p0.y; dp[2] = p1.x; dp[3] = p1.y;
            dp[4] = p2.x; dp[5] = p2.y; dp[6] = p3.x; dp[7] = p3.y;
        }
        for (int i = cnt * 32 + t; i < XW2_NODES * 32; i += 256) {
            float4* dp = reinterpret_cast<float4*>(srow + i * 8);
            dp[0] = make_float4(0, 0, 0, 0);
            dp[1] = make_float4(0, 0, 0, 0);
        }
    }
    __syncthreads();
    int warp = t >> 5;
    int nb = warp * 8;
    const float4* wx4 = reinterpret_cast<const float4*>(sWx);
    const float4* wy4 = reinterpret_cast<const float4*>(sWy);
    const float4* sr4 = reinterpret_cast<const float4*>(srow);
    float2 A0[8], A1[8];
#pragma unroll
    for (int j = 0; j < 8; j++) { A0[j] = make_float2(0, 0); A1[j] = make_float2(0, 0); }
#pragma unroll 2
    for (int kq = 0; kq < 64; kq++) {
        float4 wx = wx4[kq * 32 + l];
        float4 wy = wy4[kq * 32 + l];
        float2 wx01 = make_float2(wx.x, wx.y), wx23 = make_float2(wx.z, wx.w);
        float2 wy01 = make_float2(wy.x, wy.y), wy23 = make_float2(wy.z, wy.w);
#pragma unroll
        for (int j = 0; j < 8; j++) {
            float4 h = sr4[(nb + j) * 64 + kq];
            float2 h01 = make_float2(h.x, h.y), h23 = make_float2(h.z, h.w);
            ffma2(A0[j], h01, wx01);
            ffma2(A0[j], h23, wx23);
            ffma2(A1[j], h01, wy01);
            ffma2(A1[j], h23, wy23);
        }
    }
    float s0 = as2[2 * l], s1 = as2[2 * l + 1];
    float d0 = ad2[2 * l], d1 = ad2[2 * l + 1];
#pragma unroll
    for (int j = 0; j < 8; j++) {
        float a0 = A0[j].x + A0[j].y;
        float a1 = A1[j].x + A1[j].y;
        int node = base + nb + j;
        bool ok = node < n;
        if (ok) {
            *reinterpret_cast<__nv_bfloat162*>(g_xw2b + (size_t)node * 64 + 2 * l) =
                __floats2bfloat162_rn(a0, a1);
        }
        float vs = a0 * s0 + a1 * s1;
        float vd = a0 * d0 + a1 * d1;
#pragma unroll
        for (int o = 16; o; o >>= 1) {
            vs += __shfl_down_sync(0xffffffffu, vs, o);
            vd += __shfl_down_sync(0xffffffffu, vd, o);
        }
        if (l == 0 && ok) { g_als2[node] = vs; g_ald2[node] = vd; }
    }
}

// ---- conv2 gather-aggregate with fused attention, 16 thr/node, bf16 rows ----
__global__ void k_gather2(int n) {
    int gt = blockIdx.x * blockDim.x + threadIdx.x;
    int node = gt >> 4;
    if (node >= n) return;
    int t = gt & 15;
    int beg = g_off[node], end = g_off[node + 1];
    float aldv = g_ald2[node];
    float ce4 = g_ce[4];
    float4 acc = make_float4(0, 0, 0, 0);
    float sw = 0.f;
    for (int i = beg; i < end; i++) {
        int2 sd = g_slot[i];
        int s = sd.x;
        float a = __int_as_float(sd.y);
        float w = __expf(lrelu(g_als2[s] + aldv + a * ce4));
        uint2 raw = *reinterpret_cast<const uint2*>(g_xw2b + (size_t)s * 64 + t * 4);
        float2 p0 = __bfloat1622float2(*reinterpret_cast<__nv_bfloat162*>(&raw.x));
        float2 p1 = __bfloat1622float2(*reinterpret_cast<__nv_bfloat162*>(&raw.y));
        acc.x = fmaf(w, p0.x, acc.x); acc.y = fmaf(w, p0.y, acc.y);
        acc.z = fmaf(w, p1.x, acc.z); acc.w = fmaf(w, p1.y, acc.w);
        sw += w;
    }
    float inv = 1.f / (sw + 1e-16f);
    acc.x *= inv; acc.y *= inv; acc.z *= inv; acc.w *= inv;
    *reinterpret_cast<float4*>(&g_out2[(size_t)node * 64 + t * 4]) = acc;
}

// ---- cluster pooling of out2 + counts + cf (register partials -> smem -> global) ----
__global__ void k_pool(const float* __restrict__ x, const int* __restrict__ assign, int n) {
    __shared__ float sz[264];
    int t = threadIdx.x;
    sz[t] = 0.f;
    if (t < 8) sz[256 + t] = 0.f;
    __syncthreads();
    int gt0 = blockIdx.x * blockDim.x + t;
    int ch = gt0 & 63;
    float r0 = 0, r1 = 0, r2 = 0, r3 = 0;
    float c0 = 0, c1 = 0, c2 = 0, c3 = 0;
    float f0 = 0, f1 = 0, f2 = 0, f3 = 0;
    int total = n * 64;
    int stride = gridDim.x * blockDim.x;    // multiple of 64 by construction
    for (int idx = gt0; idx < total; idx += stride) {
        int node = idx >> 6;
        int a = assign[node];
        float v = g_out2[idx];
        if (a == 0) r0 += v; else if (a == 1) r1 += v; else if (a == 2) r2 += v; else r3 += v;
        if (ch == 0) {
            float cf = x[node * 7 + 6];
            if (a == 0) { c0 += 1.f; f0 += cf; }
            else if (a == 1) { c1 += 1.f; f1 += cf; }
            else if (a == 2) { c2 += 1.f; f2 += cf; }
            else { c3 += 1.f; f3 += cf; }
        }
    }
    atomicAdd(&sz[0 * 64 + ch], r0);
    atomicAdd(&sz[1 * 64 + ch], r1);
    atomicAdd(&sz[2 * 64 + ch], r2);
    atomicAdd(&sz[3 * 64 + ch], r3);
    if (ch == 0) {
        atomicAdd(&sz[256 + 0], c0); atomicAdd(&sz[256 + 1], c1);
        atomicAdd(&sz[256 + 2], c2); atomicAdd(&sz[256 + 3], c3);
        atomicAdd(&sz[260 + 0], f0); atomicAdd(&sz[260 + 1], f1);
        atomicAdd(&sz[260 + 2], f2); atomicAdd(&sz[260 + 3], f3);
    }
    __syncthreads();
    atomicAdd(&g_pool[t], sz[t]);
    if (t < 8) atomicAdd(&g_pool[256 + t], sz[256 + t]);
}

// ---- final: means + MLP + softmax + write output (1 block, 64 threads) ----
__global__ void k_final(const float* __restrict__ b2, const float* __restrict__ A1,
                        const float* __restrict__ c1, const float* __restrict__ A2,
                        const float* __restrict__ c2, float* __restrict__ out) {
    __shared__ float z[4][64];
    __shared__ float red[64];
    __shared__ float logits[4];
    __shared__ float probs[4];
    int t = threadIdx.x;
    float cf[4];
#pragma unroll
    for (int k = 0; k < 4; k++) {
        float cn = g_pool[256 + k];
        z[k][t] = (cn > 0.f) ? (g_pool[k * 64 + t] / cn + b2[t]) : 0.f;
        cf[k] = (cn > 0.f) ? (g_pool[260 + k] / cn) : 0.f;
    }
    __syncthreads();
    for (int k = 0; k < 4; k++) {
        float acc = c1[t];
        for (int i = 0; i < 64; i++) acc = fmaf(z[k][i], A1[i * 64 + t], acc);
        acc = fmaf(cf[k], A1[64 * 64 + t], acc);
        acc = fmaxf(acc, 0.f) * A2[t];
        red[t] = acc;
        __syncthreads();
        if (t == 0) {
            float s = 0.f;
            for (int i = 0; i < 64; i++) s += red[i];
            logits[k] = s + c2[0];
        }
        __syncthreads();
    }
    if (t == 0) {
        float m = fmaxf(fmaxf(logits[0], logits[1]), fmaxf(logits[2], logits[3]));
        float e0 = expf(logits[0] - m), e1 = expf(logits[1] - m);
        float e2 = expf(logits[2] - m), e3 = expf(logits[3] - m);
        float inv = 1.f / (e0 + e1 + e2 + e3);
        probs[0] = e0 * inv; probs[1] = e1 * inv; probs[2] = e2 * inv; probs[3] = e3 * inv;
    }
    __syncthreads();
    if (t < 4) out[t] = probs[t];
#pragma unroll
    for (int k = 0; k < 4; k++) out[4 + k * 64 + t] = z[k][t];
}

extern "C" void kernel_launch(void* const* d_in, const int* in_sizes, int n_in,
                              void* d_out, int out_size) {
    const float* x    = (const float*)d_in[0];
    const int*   ei   = (const int*)d_in[1];
    const float* ea   = (const float*)d_in[2];
    const int*   assign = (const int*)d_in[3];
    const float* W1   = (const float*)d_in[4];
    const float* as1  = (const float*)d_in[5];
    const float* ad1  = (const float*)d_in[6];
    const float* We1  = (const float*)d_in[7];
    const float* ae1  = (const float*)d_in[8];
    const float* b1   = (const float*)d_in[9];
    const float* W2   = (const float*)d_in[10];
    const float* as2  = (const float*)d_in[11];
    const float* ad2  = (const float*)d_in[12];
    const float* We2  = (const float*)d_in[13];
    const float* ae2  = (const float*)d_in[14];
    const float* b2   = (const float*)d_in[15];
    const float* A1   = (const float*)d_in[16];
    const float* c1   = (const float*)d_in[17];
    const float* A2   = (const float*)d_in[18];
    const float* c2   = (const float*)d_in[19];
    float* out = (float*)d_out;

    int n = in_sizes[0] / 7;
    int e = in_sizes[2];
    const int* src = ei;
    const int* dst = ei + e;
    int tot = e + n;
    int nb = (n + SCAN_CHUNK - 1) / SCAN_CHUNK;

    k_init<<<208, 256>>>(We1, ae1, We2, ae2, n);
    k_degloop<<<(tot + 255) / 256, 256>>>(dst, ea, e, n);
    k_xw1<<<(n + 7) / 8, 256>>>(x, W1, as1, ad1, n);
    k_part<<<nb, 1024>>>(n);
    k_offs<<<nb, 1024>>>(n, tot, nb);
    k_fill<<<(tot + 255) / 256, 256>>>(src, dst, ea, e, n);
    k_gather1<<<(n * 32 + 255) / 256, 256>>>(b1, n);

    cudaFuncSetAttribute(k_xw2, cudaFuncAttributeMaxDynamicSharedMemorySize, 131072);
    k_xw2<<<(n + XW2_NODES - 1) / XW2_NODES, 256, 131072>>>(W2, as2, ad2, n);

    k_gather2<<<(n * 16 + 255) / 256, 256>>>(n);
    k_pool<<<1184, 256>>>(x, assign, n);
    k_final<<<1, 64>>>(b2, A1, c1, A2, c2, out);
}

// round 7
// speedup vs baseline: 1.7793x; 1.0291x over previous
#include <cuda_runtime.h>
#include <cuda_bf16.h>
#include <cuda_fp8.h>
#include <math.h>

#define MAXN 50048
#define MAXE 800000
#define MAXT (MAXE + MAXN)
#define SCAN_CHUNK 4096

// ---- scratch (static __device__, no allocations) ----
__device__ __align__(16) unsigned char g_xw1f8[MAXN * 256];
__device__ __align__(16) float g_als1[MAXN * 4];
__device__ __align__(16) float g_ald1[MAXN * 4];
__device__ float g_loop_sum[MAXN];
__device__ int   g_dcnt[MAXN];
__device__ int   g_off[MAXN + 1];
__device__ int   g_cur[MAXN];
__device__ __align__(8)  int2  g_slot[MAXT];     // (src, ea-bits) per adjacency slot
__device__ int   g_bsum[64];
__device__ __align__(16) __nv_bfloat16 g_h1b[MAXN * 256];
__device__ __align__(16) __nv_bfloat16 g_xw2b[MAXN * 64];
__device__ float g_als2[MAXN];
__device__ float g_ald2[MAXN];
__device__ float g_ce[5];
__device__ float g_pool[264];   // [0:256) zsum[4][64], [256:260) cnt, [260:264) cf

__device__ __forceinline__ float lrelu(float x) { return x > 0.f ? x : 0.2f * x; }
__device__ __forceinline__ float eluf(float x)  { return x > 0.f ? x : (expf(x) - 1.f); }

__device__ __forceinline__ float2 f8x2tof2(unsigned short v) {
    __half2_raw hr = __nv_cvt_fp8x2_to_halfraw2((__nv_fp8x2_storage_t)v, __NV_E4M3);
    return __half22float2(*reinterpret_cast<__half2*>(&hr));
}
__device__ __forceinline__ unsigned short f2tof8x2(float a, float b) {
    return (unsigned short)__nv_cvt_float2_to_fp8x2(make_float2(a, b),
                                                    __NV_SATFINITE, __NV_E4M3);
}

// packed dual-fp32 FMA (B300 f32x2 pipe; PTX-only form)
__device__ __forceinline__ void ffma2(float2& d, const float2 a, const float2 b) {
    unsigned long long aa, bb;
    memcpy(&aa, &a, 8);
    memcpy(&bb, &b, 8);
    unsigned long long& dd = reinterpret_cast<unsigned long long&>(d);
    asm("fma.rn.f32x2 %0, %1, %2, %0;" : "+l"(dd) : "l"(aa), "l"(bb));
}

// ---- init: zero scratch + compute per-head edge-attention constants ----
__global__ void k_init(const float* __restrict__ We1, const float* __restrict__ ae1,
                       const float* __restrict__ We2, const float* __restrict__ ae2, int n) {
    int gt = blockIdx.x * blockDim.x + threadIdx.x;
    int stride = gridDim.x * blockDim.x;
    for (int i = gt; i < n; i += stride) {
        g_loop_sum[i] = 0.f;
        g_dcnt[i] = 0;
    }
    if (gt < 264) g_pool[gt] = 0.f;
    if (blockIdx.x == 0) {
        __shared__ float s[5];
        int t = threadIdx.x;
        if (t < 5) s[t] = 0.f;
        __syncthreads();
        if (t < 256) atomicAdd(&s[t >> 6], We1[t] * ae1[t]);
        if (t < 64) atomicAdd(&s[4], We2[t] * ae2[t]);
        __syncthreads();
        if (t < 5) g_ce[t] = s[t];
    }
}

// ---- per-dst degree + self-loop attr sums + cluster cnt/cf (smem staged) ----
__global__ void k_degloop(const int* __restrict__ dst, const float* __restrict__ ea,
                          const float* __restrict__ x, const int* __restrict__ assign,
                          int e, int n) {
    __shared__ float s8[8];
    int t = threadIdx.x;
    if (t < 8) s8[t] = 0.f;
    __syncthreads();
    int idx = blockIdx.x * blockDim.x + t;
    if (idx < e) {
        int d = dst[idx];
        atomicAdd(&g_loop_sum[d], ea[idx]);
        atomicAdd(&g_dcnt[d], 1);
    } else if (idx < e + n) {
        int node = idx - e;
        atomicAdd(&g_dcnt[node], 1);
        int a = assign[node];
        atomicAdd(&s8[a], 1.f);
        atomicAdd(&s8[4 + a], x[node * 7 + 6]);
    }
    __syncthreads();
    if (t < 8 && s8[t] != 0.f) atomicAdd(&g_pool[256 + t], s8[t]);
}

// ---- device-wide exclusive scan, stage 1: per-block sums (1024 thr, 4096 elems) ----
__global__ void k_part(int n) {
    int t = threadIdx.x;
    int base = blockIdx.x * SCAN_CHUNK + t * 4;
    int s = 0;
#pragma unroll
    for (int i = 0; i < 4; i++) {
        int idx = base + i;
        if (idx < n) s += g_dcnt[idx];
    }
#pragma unroll
    for (int o = 16; o; o >>= 1) s += __shfl_down_sync(0xffffffffu, s, o);
    __shared__ int ws[32];
    if ((t & 31) == 0) ws[t >> 5] = s;
    __syncthreads();
    if (t < 32) {
        int v = ws[t];
#pragma unroll
        for (int o = 16; o; o >>= 1) v += __shfl_down_sync(0xffffffffu, v, o);
        if (t == 0) g_bsum[blockIdx.x] = v;
    }
}

// ---- stage 2: block-local scan (+ inline scan of block sums) -> offsets/cursors ----
__global__ void k_offs(int n, int tot, int nb) {
    int t = threadIdx.x;
    __shared__ int spre[32];
    if (t < 32) {
        int s = (t < nb) ? g_bsum[t] : 0;
        int v = s;
#pragma unroll
        for (int o = 1; o < 32; o <<= 1) {
            int u = __shfl_up_sync(0xffffffffu, v, o);
            if (t >= o) v += u;
        }
        spre[t] = v - s;
    }
    int base = blockIdx.x * SCAN_CHUNK + t * 4;
    int v[4];
    int s = 0;
#pragma unroll
    for (int i = 0; i < 4; i++) {
        int idx = base + i;
        v[i] = (idx < n) ? g_dcnt[idx] : 0;
        s += v[i];
    }
    int lane = t & 31, w = t >> 5;
    int ps = s;
#pragma unroll
    for (int o = 1; o < 32; o <<= 1) {
        int u = __shfl_up_sync(0xffffffffu, ps, o);
        if (lane >= o) ps += u;
    }
    __shared__ int ws[32];
    if (lane == 31) ws[w] = ps;
    __syncthreads();
    if (t < 32) {
        int x = ws[t];
#pragma unroll
        for (int o = 1; o < 32; o <<= 1) {
            int u = __shfl_up_sync(0xffffffffu, x, o);
            if (t >= o) x += u;
        }
        ws[t] = x;
    }
    __syncthreads();
    int excl = ps - s + (w ? ws[w - 1] : 0) + spre[blockIdx.x];
#pragma unroll
    for (int i = 0; i < 4; i++) {
        int idx = base + i;
        if (idx < n) {
            g_off[idx] = excl;
            g_cur[idx] = excl;
            excl += v[i];
        }
    }
    if (blockIdx.x == 0 && t == 0) g_off[n] = tot;
}

// ---- xw1 = x @ W1 (+ fused al_src1 / al_dst1), one warp per node, fp8 store ----
__global__ void k_xw1(const float* __restrict__ x, const float* __restrict__ W1,
                      const float* __restrict__ as1, const float* __restrict__ ad1, int n) {
    __shared__ float sW[7 * 256];
    __shared__ float sA[256];
    __shared__ float sB[256];
    int t = threadIdx.x;
    for (int i = t; i < 7 * 256; i += blockDim.x) sW[i] = W1[i];
    if (t < 256) { sA[t] = as1[t]; sB[t] = ad1[t]; }
    __syncthreads();
    int node = (blockIdx.x * blockDim.x + t) >> 5;
    int lane = t & 31;
    if (node >= n) return;
    float xv[7];
#pragma unroll
    for (int i = 0; i < 7; i++) xv[i] = x[node * 7 + i];
    const float2* sW2 = reinterpret_cast<const float2*>(sW);
    const float2* sA2 = reinterpret_cast<const float2*>(sA);
    const float2* sB2 = reinterpret_cast<const float2*>(sB);
    float accs[4], accd[4];
    unsigned short* ob = reinterpret_cast<unsigned short*>(g_xw1f8 + (size_t)node * 256);
#pragma unroll
    for (int k = 0; k < 4; k++) {
        int p = k * 32 + lane;                 // pair index within 128-wide row
        float v0 = 0.f, v1 = 0.f;
#pragma unroll
        for (int i = 0; i < 7; i++) {
            float2 wv = sW2[i * 128 + p];
            v0 = fmaf(xv[i], wv.x, v0);
            v1 = fmaf(xv[i], wv.y, v1);
        }
        float2 av = sA2[p], bv = sB2[p];
        accs[k] = fmaf(v0, av.x, v1 * av.y);
        accd[k] = fmaf(v0, bv.x, v1 * bv.y);
        ob[p] = f2tof8x2(v0, v1);
    }
#pragma unroll
    for (int h = 0; h < 4; h++) {
        float vs = accs[h], vd = accd[h];
#pragma unroll
        for (int o = 16; o; o >>= 1) {
            vs += __shfl_down_sync(0xffffffffu, vs, o);
            vd += __shfl_down_sync(0xffffffffu, vd, o);
        }
        if (lane == 0) { g_als1[node * 4 + h] = vs; g_ald1[node * 4 + h] = vd; }
    }
}

// ---- fill adjacency: slot gets (src, ea-bits); slim, no attention math ----
__global__ void k_fill(const int* __restrict__ src, const int* __restrict__ dst,
                       const float* __restrict__ ea, int e, int n) {
    int idx = blockIdx.x * blockDim.x + threadIdx.x;
    if (idx >= e + n) return;
    int d, s; float a;
    if (idx < e) { d = dst[idx]; s = src[idx]; a = ea[idx]; }
    else {
        d = idx - e; s = d;
        float cnt = (float)(g_dcnt[d] - 1);
        a = g_loop_sum[d] / fmaxf(cnt, 1.f);
    }
    int p = atomicAdd(&g_cur[d], 1);
    g_slot[p] = make_int2(s, __float_as_int(a));
}

// ---- conv1 gather-aggregate, 32 thr/node, fp8 rows, inline attention ----
__global__ void k_gather1(const float* __restrict__ b1, int n) {
    int gt = blockIdx.x * blockDim.x + threadIdx.x;
    int node = gt >> 5;
    if (node >= n) return;
    int l = gt & 31, h = l >> 3;
    int beg = g_off[node], end = g_off[node + 1];
    float ald_h = g_ald1[node * 4 + h];
    float ce_h = g_ce[h];
    float acc0 = 0, acc1 = 0, acc2 = 0, acc3 = 0, acc4 = 0, acc5 = 0, acc6 = 0, acc7 = 0;
    float sw = 0.f;
    for (int i = beg; i < end; i++) {
        int2 sd = g_slot[i];
        int s = sd.x;
        float a = __int_as_float(sd.y);
        float lg = g_als1[s * 4 + h] + ald_h + a * ce_h;
        float w = __expf(lrelu(lg));
        uint2 raw = *reinterpret_cast<const uint2*>(g_xw1f8 + (size_t)s * 256 + l * 8);
        float2 p0 = f8x2tof2((unsigned short)(raw.x & 0xffffu));
        float2 p1 = f8x2tof2((unsigned short)(raw.x >> 16));
        float2 p2 = f8x2tof2((unsigned short)(raw.y & 0xffffu));
        float2 p3 = f8x2tof2((unsigned short)(raw.y >> 16));
        acc0 = fmaf(w, p0.x, acc0); acc1 = fmaf(w, p0.y, acc1);
        acc2 = fmaf(w, p1.x, acc2); acc3 = fmaf(w, p1.y, acc3);
        acc4 = fmaf(w, p2.x, acc4); acc5 = fmaf(w, p2.y, acc5);
        acc6 = fmaf(w, p3.x, acc6); acc7 = fmaf(w, p3.y, acc7);
        sw += w;
    }
    float inv = 1.f / (sw + 1e-16f);
    const float4* b4 = reinterpret_cast<const float4*>(b1);
    float4 ba = b4[l * 2], bb = b4[l * 2 + 1];
    float o0 = eluf(acc0 * inv + ba.x), o1 = eluf(acc1 * inv + ba.y);
    float o2 = eluf(acc2 * inv + ba.z), o3 = eluf(acc3 * inv + ba.w);
    float o4 = eluf(acc4 * inv + bb.x), o5 = eluf(acc5 * inv + bb.y);
    float o6 = eluf(acc6 * inv + bb.z), o7 = eluf(acc7 * inv + bb.w);
    uint4 outw;
    *reinterpret_cast<__nv_bfloat162*>(&outw.x) = __floats2bfloat162_rn(o0, o1);
    *reinterpret_cast<__nv_bfloat162*>(&outw.y) = __floats2bfloat162_rn(o2, o3);
    *reinterpret_cast<__nv_bfloat162*>(&outw.z) = __floats2bfloat162_rn(o4, o5);
    *reinterpret_cast<__nv_bfloat162*>(&outw.w) = __floats2bfloat162_rn(o6, o7);
    *reinterpret_cast<uint4*>(g_h1b + (size_t)node * 256 + l * 8) = outw;
}

// ---- xw2 = h1 @ W2 via packed f32x2 FMA. 64 nodes/block, bf16 store ----
#define XW2_NODES 64
__global__ void k_xw2(const float* __restrict__ W2, const float* __restrict__ as2,
                      const float* __restrict__ ad2, int n) {
    extern __shared__ float sm[];
    float* sWx = sm;                 // 32KB: [kq*128 + 4l + c] = W2[(4kq+c)*64 + 2l]
    float* sWy = sm + 8192;          // 32KB: same, col 2l+1
    float* srow = sm + 16384;        // 64KB: 64 rows x 256 fp32
    int t = threadIdx.x;             // 256 threads
    int l = t & 31;
    {
        const float2* w2v = reinterpret_cast<const float2*>(W2);
        for (int k = t >> 5; k < 256; k += 8) {
            float2 w = w2v[k * 32 + l];          // (W2[k][2l], W2[k][2l+1]) coalesced
            int a = (k >> 2) * 128 + l * 4 + (k & 3);
            sWx[a] = w.x;
            sWy[a] = w.y;
        }
    }
    int base = blockIdx.x * XW2_NODES;
    int cnt = min(XW2_NODES, n - base);
    {
        const uint4* h4 = reinterpret_cast<const uint4*>(g_h1b + (size_t)base * 256);
        for (int i = t; i < cnt * 32; i += 256) {
            uint4 raw = h4[i];
            float* dp = srow + i * 8;
            float2 p0 = __bfloat1622float2(*reinterpret_cast<__nv_bfloat162*>(&raw.x));
            float2 p1 = __bfloat1622float2(*reinterpret_cast<__nv_bfloat162*>(&raw.y));
            float2 p2 = __bfloat1622float2(*reinterpret_cast<__nv_bfloat162*>(&raw.z));
            float2 p3 = __bfloat1622float2(*reinterpret_cast<__nv_bfloat162*>(&raw.w));
            dp[0] = p0.x; dp[1] = p0.y; dp[2] = p1.x; dp[3] = p1.y;
            dp[4] = p2.x; dp[5] = p2.y; dp[6] = p3.x; dp[7] = p3.y;
        }
        for (int i = cnt * 32 + t; i < XW2_NODES * 32; i += 256) {
            float4* dp = reinterpret_cast<float4*>(srow + i * 8);
            dp[0] = make_float4(0, 0, 0, 0);
            dp[1] = make_float4(0, 0, 0, 0);
        }
    }
    __syncthreads();
    int warp = t >> 5;
    int nb = warp * 8;
    const float4* wx4 = reinterpret_cast<const float4*>(sWx);
    const float4* wy4 = reinterpret_cast<const float4*>(sWy);
    const float4* sr4 = reinterpret_cast<const float4*>(srow);
    float2 A0[8], A1[8];
#pragma unroll
    for (int j = 0; j < 8; j++) { A0[j] = make_float2(0, 0); A1[j] = make_float2(0, 0); }
#pragma unroll 2
    for (int kq = 0; kq < 64; kq++) {
        float4 wx = wx4[kq * 32 + l];
        float4 wy = wy4[kq * 32 + l];
        float2 wx01 = make_float2(wx.x, wx.y), wx23 = make_float2(wx.z, wx.w);
        float2 wy01 = make_float2(wy.x, wy.y), wy23 = make_float2(wy.z, wy.w);
#pragma unroll
        for (int j = 0; j < 8; j++) {
            float4 h = sr4[(nb + j) * 64 + kq];
            float2 h01 = make_float2(h.x, h.y), h23 = make_float2(h.z, h.w);
            ffma2(A0[j], h01, wx01);
            ffma2(A0[j], h23, wx23);
            ffma2(A1[j], h01, wy01);
            ffma2(A1[j], h23, wy23);
        }
    }
    float s0 = as2[2 * l], s1 = as2[2 * l + 1];
    float d0 = ad2[2 * l], d1 = ad2[2 * l + 1];
#pragma unroll
    for (int j = 0; j < 8; j++) {
        float a0 = A0[j].x + A0[j].y;
        float a1 = A1[j].x + A1[j].y;
        int node = base + nb + j;
        bool ok = node < n;
        if (ok) {
            *reinterpret_cast<__nv_bfloat162*>(g_xw2b + (size_t)node * 64 + 2 * l) =
                __floats2bfloat162_rn(a0, a1);
        }
        float vs = a0 * s0 + a1 * s1;
        float vd = a0 * d0 + a1 * d1;
#pragma unroll
        for (int o = 16; o; o >>= 1) {
            vs += __shfl_down_sync(0xffffffffu, vs, o);
            vd += __shfl_down_sync(0xffffffffu, vd, o);
        }
        if (l == 0 && ok) { g_als2[node] = vs; g_ald2[node] = vd; }
    }
}

// ---- conv2 gather + fused attention + fused cluster pooling (no out2 array) ----
__global__ void k_gather2(const int* __restrict__ assign, int n) {
    __shared__ float sval[64 * 65];
    __shared__ int   sa[64];
    int t = threadIdx.x;            // 1024 threads, 64 nodes/block
    int nl = t >> 4;
    int c = t & 15;
    int node = blockIdx.x * 64 + nl;
    float4 acc = make_float4(0, 0, 0, 0);
    if (node < n) {
        int beg = g_off[node], end = g_off[node + 1];
        float aldv = g_ald2[node];
        float ce4 = g_ce[4];
        float sw = 0.f;
        for (int i = beg; i < end; i++) {
            int2 sd = g_slot[i];
            int s = sd.x;
            float a = __int_as_float(sd.y);
            float w = __expf(lrelu(g_als2[s] + aldv + a * ce4));
            uint2 raw = *reinterpret_cast<const uint2*>(g_xw2b + (size_t)s * 64 + c * 4);
            float2 p0 = __bfloat1622float2(*reinterpret_cast<__nv_bfloat162*>(&raw.x));
            float2 p1 = __bfloat1622float2(*reinterpret_cast<__nv_bfloat162*>(&raw.y));
            acc.x = fmaf(w, p0.x, acc.x); acc.y = fmaf(w, p0.y, acc.y);
            acc.z = fmaf(w, p1.x, acc.z); acc.w = fmaf(w, p1.y, acc.w);
            sw += w;
        }
        float inv = 1.f / (sw + 1e-16f);
        acc.x *= inv; acc.y *= inv; acc.z *= inv; acc.w *= inv;
        if (c == 0) sa[nl] = assign[node];
    } else if (c == 0) {
        sa[nl] = -1;
    }
    float* vp = &sval[nl * 65 + c * 4];
    vp[0] = acc.x; vp[1] = acc.y; vp[2] = acc.z; vp[3] = acc.w;
    __syncthreads();
    if (t < 256) {
        int k = t >> 6, ch = t & 63;
        float s = 0.f;
        for (int j = 0; j < 64; j++) {
            float v = sval[j * 65 + ch];
            if (sa[j] == k) s += v;
        }
        if (s != 0.f) atomicAdd(&g_pool[k * 64 + ch], s);
    }
}

// ---- final: means + MLP + softmax + write output (1 block, 64 threads) ----
__global__ void k_final(const float* __restrict__ b2, const float* __restrict__ A1,
                        const float* __restrict__ c1, const float* __restrict__ A2,
                        const float* __restrict__ c2, float* __restrict__ out) {
    __shared__ float z[4][64];
    __shared__ float red[64];
    __shared__ float logits[4];
    __shared__ float probs[4];
    int t = threadIdx.x;
    float cf[4];
#pragma unroll
    for (int k = 0; k < 4; k++) {
        float cn = g_pool[256 + k];
        z[k][t] = (cn > 0.f) ? (g_pool[k * 64 + t] / cn + b2[t]) : 0.f;
        cf[k] = (cn > 0.f) ? (g_pool[260 + k] / cn) : 0.f;
    }
    __syncthreads();
    for (int k = 0; k < 4; k++) {
        float acc = c1[t];
        for (int i = 0; i < 64; i++) acc = fmaf(z[k][i], A1[i * 64 + t], acc);
        acc = fmaf(cf[k], A1[64 * 64 + t], acc);
        acc = fmaxf(acc, 0.f) * A2[t];
        red[t] = acc;
        __syncthreads();
        if (t == 0) {
            float s = 0.f;
            for (int i = 0; i < 64; i++) s += red[i];
            logits[k] = s + c2[0];
        }
        __syncthreads();
    }
    if (t == 0) {
        float m = fmaxf(fmaxf(logits[0], logits[1]), fmaxf(logits[2], logits[3]));
        float e0 = expf(logits[0] - m), e1 = expf(logits[1] - m);
        float e2 = expf(logits[2] - m), e3 = expf(logits[3] - m);
        float inv = 1.f / (e0 + e1 + e2 + e3);
        probs[0] = e0 * inv; probs[1] = e1 * inv; probs[2] = e2 * inv; probs[3] = e3 * inv;
    }
    __syncthreads();
    if (t < 4) out[t] = probs[t];
#pragma unroll
    for (int k = 0; k < 4; k++) out[4 + k * 64 + t] = z[k][t];
}

extern "C" void kernel_launch(void* const* d_in, const int* in_sizes, int n_in,
                              void* d_out, int out_size) {
    const float* x    = (const float*)d_in[0];
    const int*   ei   = (const int*)d_in[1];
    const float* ea   = (const float*)d_in[2];
    const int*   assign = (const int*)d_in[3];
    const float* W1   = (const float*)d_in[4];
    const float* as1  = (const float*)d_in[5];
    const float* ad1  = (const float*)d_in[6];
    const float* We1  = (const float*)d_in[7];
    const float* ae1  = (const float*)d_in[8];
    const float* b1   = (const float*)d_in[9];
    const float* W2   = (const float*)d_in[10];
    const float* as2  = (const float*)d_in[11];
    const float* ad2  = (const float*)d_in[12];
    const float* We2  = (const float*)d_in[13];
    const float* ae2  = (const float*)d_in[14];
    const float* b2   = (const float*)d_in[15];
    const float* A1   = (const float*)d_in[16];
    const float* c1   = (const float*)d_in[17];
    const float* A2   = (const float*)d_in[18];
    const float* c2   = (const float*)d_in[19];
    float* out = (float*)d_out;

    int n = in_sizes[0] / 7;
    int e = in_sizes[2];
    const int* src = ei;
    const int* dst = ei + e;
    int tot = e + n;
    int nb = (n + SCAN_CHUNK - 1) / SCAN_CHUNK;

    k_init<<<208, 256>>>(We1, ae1, We2, ae2, n);
    k_degloop<<<(tot + 255) / 256, 256>>>(dst, ea, x, assign, e, n);
    k_xw1<<<(n + 7) / 8, 256>>>(x, W1, as1, ad1, n);
    k_part<<<nb, 1024>>>(n);
    k_offs<<<nb, 1024>>>(n, tot, nb);
    k_fill<<<(tot + 255) / 256, 256>>>(src, dst, ea, e, n);
    k_gather1<<<(n * 32 + 255) / 256, 256>>>(b1, n);

    cudaFuncSetAttribute(k_xw2, cudaFuncAttributeMaxDynamicSharedMemorySize, 131072);
    k_xw2<<<(n + XW2_NODES - 1) / XW2_NODES, 256, 131072>>>(W2, as2, ad2, n);

    k_gather2<<<(n + 63) / 64, 1024>>>(assign, n);
    k_final<<<1, 64>>>(b2, A1, c1, A2, c2, out);
}

// round 8
// speedup vs baseline: 1.8319x; 1.0295x over previous
#include <cuda_runtime.h>
#include <cuda_bf16.h>
#include <cuda_fp8.h>
#include <math.h>

#define MAXN 50048
#define MAXE 800000
#define MAXT (MAXE + MAXN)
#define SCAN_CHUNK 4096

// ---- scratch (static __device__, no allocations) ----
__device__ __align__(16) unsigned char g_xw1f8[MAXN * 256];
__device__ __align__(16) float g_als1[MAXN * 4];
__device__ __align__(16) float g_ald1[MAXN * 4];
__device__ float g_loop_sum[MAXN];
__device__ int   g_dcnt[MAXN];
__device__ int   g_off[MAXN + 1];
__device__ int   g_cur[MAXN];
__device__ __align__(8)  int2  g_slot[MAXT];     // (src, ea-bits) per adjacency slot
__device__ int   g_bsum[64];
__device__ __align__(16) __nv_bfloat16 g_h1b[MAXN * 256];
__device__ __align__(16) __nv_bfloat16 g_xw2b[MAXN * 64];
__device__ float g_als2[MAXN];
__device__ float g_ald2[MAXN];
__device__ float g_ce[5];
__device__ float g_pool[264];   // [0:256) zsum[4][64], [256:260) cnt, [260:264) cf

__device__ __forceinline__ float lrelu(float x) { return x > 0.f ? x : 0.2f * x; }
__device__ __forceinline__ float eluf(float x)  { return x > 0.f ? x : (expf(x) - 1.f); }

__device__ __forceinline__ float2 f8x2tof2(unsigned short v) {
    __half2_raw hr = __nv_cvt_fp8x2_to_halfraw2((__nv_fp8x2_storage_t)v, __NV_E4M3);
    return __half22float2(*reinterpret_cast<__half2*>(&hr));
}
__device__ __forceinline__ unsigned short f2tof8x2(float a, float b) {
    return (unsigned short)__nv_cvt_float2_to_fp8x2(make_float2(a, b),
                                                    __NV_SATFINITE, __NV_E4M3);
}

// packed dual-fp32 FMA (B300 f32x2 pipe; PTX-only form)
__device__ __forceinline__ void ffma2(float2& d, const float2 a, const float2 b) {
    unsigned long long aa, bb;
    memcpy(&aa, &a, 8);
    memcpy(&bb, &b, 8);
    unsigned long long& dd = reinterpret_cast<unsigned long long&>(d);
    asm("fma.rn.f32x2 %0, %1, %2, %0;" : "+l"(dd) : "l"(aa), "l"(bb));
}

// ---- init: zero scratch + compute per-head edge-attention constants ----
__global__ void k_init(const float* __restrict__ We1, const float* __restrict__ ae1,
                       const float* __restrict__ We2, const float* __restrict__ ae2, int n) {
    int gt = blockIdx.x * blockDim.x + threadIdx.x;
    int stride = gridDim.x * blockDim.x;
    for (int i = gt; i < n; i += stride) {
        g_loop_sum[i] = 0.f;
        g_dcnt[i] = 0;
    }
    if (gt < 264) g_pool[gt] = 0.f;
    if (blockIdx.x == 0) {
        __shared__ float s[5];
        int t = threadIdx.x;
        if (t < 5) s[t] = 0.f;
        __syncthreads();
        if (t < 256) atomicAdd(&s[t >> 6], We1[t] * ae1[t]);
        if (t < 64) atomicAdd(&s[4], We2[t] * ae2[t]);
        __syncthreads();
        if (t < 5) g_ce[t] = s[t];
    }
}

// ---- per-dst degree + self-loop attr sums + cluster cnt/cf (smem staged) ----
__global__ void k_degloop(const int* __restrict__ dst, const float* __restrict__ ea,
                          const float* __restrict__ x, const int* __restrict__ assign,
                          int e, int n) {
    __shared__ float s8[8];
    int t = threadIdx.x;
    if (t < 8) s8[t] = 0.f;
    __syncthreads();
    int idx = blockIdx.x * blockDim.x + t;
    if (idx < e) {
        int d = dst[idx];
        atomicAdd(&g_loop_sum[d], ea[idx]);
        atomicAdd(&g_dcnt[d], 1);
    } else if (idx < e + n) {
        int node = idx - e;
        atomicAdd(&g_dcnt[node], 1);
        int a = assign[node];
        atomicAdd(&s8[a], 1.f);
        atomicAdd(&s8[4 + a], x[node * 7 + 6]);
    }
    __syncthreads();
    if (t < 8 && s8[t] != 0.f) atomicAdd(&g_pool[256 + t], s8[t]);
}

// ---- device-wide exclusive scan, stage 1: per-block sums (1024 thr, 4096 elems) ----
__global__ void k_part(int n) {
    int t = threadIdx.x;
    int base = blockIdx.x * SCAN_CHUNK + t * 4;
    int s = 0;
#pragma unroll
    for (int i = 0; i < 4; i++) {
        int idx = base + i;
        if (idx < n) s += g_dcnt[idx];
    }
#pragma unroll
    for (int o = 16; o; o >>= 1) s += __shfl_down_sync(0xffffffffu, s, o);
    __shared__ int ws[32];
    if ((t & 31) == 0) ws[t >> 5] = s;
    __syncthreads();
    if (t < 32) {
        int v = ws[t];
#pragma unroll
        for (int o = 16; o; o >>= 1) v += __shfl_down_sync(0xffffffffu, v, o);
        if (t == 0) g_bsum[blockIdx.x] = v;
    }
}

// ---- stage 2: block-local scan (+ inline scan of block sums) -> offsets/cursors ----
__global__ void k_offs(int n, int tot, int nb) {
    int t = threadIdx.x;
    __shared__ int spre[32];
    if (t < 32) {
        int s = (t < nb) ? g_bsum[t] : 0;
        int v = s;
#pragma unroll
        for (int o = 1; o < 32; o <<= 1) {
            int u = __shfl_up_sync(0xffffffffu, v, o);
            if (t >= o) v += u;
        }
        spre[t] = v - s;
    }
    int base = blockIdx.x * SCAN_CHUNK + t * 4;
    int v[4];
    int s = 0;
#pragma unroll
    for (int i = 0; i < 4; i++) {
        int idx = base + i;
        v[i] = (idx < n) ? g_dcnt[idx] : 0;
        s += v[i];
    }
    int lane = t & 31, w = t >> 5;
    int ps = s;
#pragma unroll
    for (int o = 1; o < 32; o <<= 1) {
        int u = __shfl_up_sync(0xffffffffu, ps, o);
        if (lane >= o) ps += u;
    }
    __shared__ int ws[32];
    if (lane == 31) ws[w] = ps;
    __syncthreads();
    if (t < 32) {
        int x = ws[t];
#pragma unroll
        for (int o = 1; o < 32; o <<= 1) {
            int u = __shfl_up_sync(0xffffffffu, x, o);
            if (t >= o) x += u;
        }
        ws[t] = x;
    }
    __syncthreads();
    int excl = ps - s + (w ? ws[w - 1] : 0) + spre[blockIdx.x];
#pragma unroll
    for (int i = 0; i < 4; i++) {
        int idx = base + i;
        if (idx < n) {
            g_off[idx] = excl;
            g_cur[idx] = excl;
            excl += v[i];
        }
    }
    if (blockIdx.x == 0 && t == 0) g_off[n] = tot;
}

// ---- xw1 = x @ W1 (+ fused al_src1 / al_dst1), one warp per node, fp8 store ----
__global__ void k_xw1(const float* __restrict__ x, const float* __restrict__ W1,
                      const float* __restrict__ as1, const float* __restrict__ ad1, int n) {
    __shared__ float sW[7 * 256];
    __shared__ float sA[256];
    __shared__ float sB[256];
    int t = threadIdx.x;
    for (int i = t; i < 7 * 256; i += blockDim.x) sW[i] = W1[i];
    if (t < 256) { sA[t] = as1[t]; sB[t] = ad1[t]; }
    __syncthreads();
    int node = (blockIdx.x * blockDim.x + t) >> 5;
    int lane = t & 31;
    if (node >= n) return;
    float xv[7];
#pragma unroll
    for (int i = 0; i < 7; i++) xv[i] = x[node * 7 + i];
    const float2* sW2 = reinterpret_cast<const float2*>(sW);
    const float2* sA2 = reinterpret_cast<const float2*>(sA);
    const float2* sB2 = reinterpret_cast<const float2*>(sB);
    float accs[4], accd[4];
    unsigned short* ob = reinterpret_cast<unsigned short*>(g_xw1f8 + (size_t)node * 256);
#pragma unroll
    for (int k = 0; k < 4; k++) {
        int p = k * 32 + lane;                 // pair index within 128-wide row
        float v0 = 0.f, v1 = 0.f;
#pragma unroll
        for (int i = 0; i < 7; i++) {
            float2 wv = sW2[i * 128 + p];
            v0 = fmaf(xv[i], wv.x, v0);
            v1 = fmaf(xv[i], wv.y, v1);
        }
        float2 av = sA2[p], bv = sB2[p];
        accs[k] = fmaf(v0, av.x, v1 * av.y);
        accd[k] = fmaf(v0, bv.x, v1 * bv.y);
        ob[p] = f2tof8x2(v0, v1);
    }
#pragma unroll
    for (int h = 0; h < 4; h++) {
        float vs = accs[h], vd = accd[h];
#pragma unroll
        for (int o = 16; o; o >>= 1) {
            vs += __shfl_down_sync(0xffffffffu, vs, o);
            vd += __shfl_down_sync(0xffffffffu, vd, o);
        }
        if (lane == 0) { g_als1[node * 4 + h] = vs; g_ald1[node * 4 + h] = vd; }
    }
}

// ---- fill adjacency: slot gets (src, ea-bits); slim, no attention math ----
__global__ void k_fill(const int* __restrict__ src, const int* __restrict__ dst,
                       const float* __restrict__ ea, int e, int n) {
    int idx = blockIdx.x * blockDim.x + threadIdx.x;
    if (idx >= e + n) return;
    int d, s; float a;
    if (idx < e) { d = dst[idx]; s = src[idx]; a = ea[idx]; }
    else {
        d = idx - e; s = d;
        float cnt = (float)(g_dcnt[d] - 1);
        a = g_loop_sum[d] / fmaxf(cnt, 1.f);
    }
    int p = atomicAdd(&g_cur[d], 1);
    g_slot[p] = make_int2(s, __float_as_int(a));
}

// ---- conv1 gather-aggregate, 32 thr/node, fp8 rows, 2x-unrolled edge loop ----
__global__ void k_gather1(const float* __restrict__ b1, int n) {
    int gt = blockIdx.x * blockDim.x + threadIdx.x;
    int node = gt >> 5;
    if (node >= n) return;
    int l = gt & 31, h = l >> 3;
    int beg = g_off[node], end = g_off[node + 1];
    float ald_h = g_ald1[node * 4 + h];
    float ce_h = g_ce[h];
    float a0 = 0, a1 = 0, a2 = 0, a3 = 0, a4 = 0, a5 = 0, a6 = 0, a7 = 0;
    float c0 = 0, c1 = 0, c2 = 0, c3 = 0, c4 = 0, c5 = 0, c6 = 0, c7 = 0;
    float swa = 0.f, swb = 0.f;
    int i = beg;
    for (; i + 2 <= end; i += 2) {
        int2 sdA = g_slot[i];
        int2 sdB = g_slot[i + 1];
        float lgA = g_als1[sdA.x * 4 + h] + ald_h + __int_as_float(sdA.y) * ce_h;
        float lgB = g_als1[sdB.x * 4 + h] + ald_h + __int_as_float(sdB.y) * ce_h;
        uint2 rA = *reinterpret_cast<const uint2*>(g_xw1f8 + (size_t)sdA.x * 256 + l * 8);
        uint2 rB = *reinterpret_cast<const uint2*>(g_xw1f8 + (size_t)sdB.x * 256 + l * 8);
        float wA = __expf(lrelu(lgA));
        float wB = __expf(lrelu(lgB));
        float2 pA0 = f8x2tof2((unsigned short)(rA.x & 0xffffu));
        float2 pA1 = f8x2tof2((unsigned short)(rA.x >> 16));
        float2 pA2 = f8x2tof2((unsigned short)(rA.y & 0xffffu));
        float2 pA3 = f8x2tof2((unsigned short)(rA.y >> 16));
        float2 pB0 = f8x2tof2((unsigned short)(rB.x & 0xffffu));
        float2 pB1 = f8x2tof2((unsigned short)(rB.x >> 16));
        float2 pB2 = f8x2tof2((unsigned short)(rB.y & 0xffffu));
        float2 pB3 = f8x2tof2((unsigned short)(rB.y >> 16));
        a0 = fmaf(wA, pA0.x, a0); a1 = fmaf(wA, pA0.y, a1);
        a2 = fmaf(wA, pA1.x, a2); a3 = fmaf(wA, pA1.y, a3);
        a4 = fmaf(wA, pA2.x, a4); a5 = fmaf(wA, pA2.y, a5);
        a6 = fmaf(wA, pA3.x, a6); a7 = fmaf(wA, pA3.y, a7);
        c0 = fmaf(wB, pB0.x, c0); c1 = fmaf(wB, pB0.y, c1);
        c2 = fmaf(wB, pB1.x, c2); c3 = fmaf(wB, pB1.y, c3);
        c4 = fmaf(wB, pB2.x, c4); c5 = fmaf(wB, pB2.y, c5);
        c6 = fmaf(wB, pB3.x, c6); c7 = fmaf(wB, pB3.y, c7);
        swa += wA; swb += wB;
    }
    if (i < end) {
        int2 sd = g_slot[i];
        float lg = g_als1[sd.x * 4 + h] + ald_h + __int_as_float(sd.y) * ce_h;
        float w = __expf(lrelu(lg));
        uint2 raw = *reinterpret_cast<const uint2*>(g_xw1f8 + (size_t)sd.x * 256 + l * 8);
        float2 p0 = f8x2tof2((unsigned short)(raw.x & 0xffffu));
        float2 p1 = f8x2tof2((unsigned short)(raw.x >> 16));
        float2 p2 = f8x2tof2((unsigned short)(raw.y & 0xffffu));
        float2 p3 = f8x2tof2((unsigned short)(raw.y >> 16));
        a0 = fmaf(w, p0.x, a0); a1 = fmaf(w, p0.y, a1);
        a2 = fmaf(w, p1.x, a2); a3 = fmaf(w, p1.y, a3);
        a4 = fmaf(w, p2.x, a4); a5 = fmaf(w, p2.y, a5);
        a6 = fmaf(w, p3.x, a6); a7 = fmaf(w, p3.y, a7);
        swa += w;
    }
    a0 += c0; a1 += c1; a2 += c2; a3 += c3;
    a4 += c4; a5 += c5; a6 += c6; a7 += c7;
    float sw = swa + swb;
    float inv = 1.f / (sw + 1e-16f);
    const float4* b4 = reinterpret_cast<const float4*>(b1);
    float4 ba = b4[l * 2], bb = b4[l * 2 + 1];
    float o0 = eluf(a0 * inv + ba.x), o1 = eluf(a1 * inv + ba.y);
    float o2 = eluf(a2 * inv + ba.z), o3 = eluf(a3 * inv + ba.w);
    float o4 = eluf(a4 * inv + bb.x), o5 = eluf(a5 * inv + bb.y);
    float o6 = eluf(a6 * inv + bb.z), o7 = eluf(a7 * inv + bb.w);
    uint4 outw;
    *reinterpret_cast<__nv_bfloat162*>(&outw.x) = __floats2bfloat162_rn(o0, o1);
    *reinterpret_cast<__nv_bfloat162*>(&outw.y) = __floats2bfloat162_rn(o2, o3);
    *reinterpret_cast<__nv_bfloat162*>(&outw.z) = __floats2bfloat162_rn(o4, o5);
    *reinterpret_cast<__nv_bfloat162*>(&outw.w) = __floats2bfloat162_rn(o6, o7);
    *reinterpret_cast<uint4*>(g_h1b + (size_t)node * 256 + l * 8) = outw;
}

// ---- xw2 = h1 @ W2 via packed f32x2 FMA. 64 nodes/block, bf16 store ----
#define XW2_NODES 64
__global__ void k_xw2(const float* __restrict__ W2, const float* __restrict__ as2,
                      const float* __restrict__ ad2, int n) {
    extern __shared__ float sm[];
    float* sWx = sm;                 // 32KB: [kq*128 + 4l + c] = W2[(4kq+c)*64 + 2l]
    float* sWy = sm + 8192;          // 32KB: same, col 2l+1
    float* srow = sm + 16384;        // 64KB: 64 rows x 256 fp32
    int t = threadIdx.x;             // 256 threads
    int l = t & 31;
    {
        const float2* w2v = reinterpret_cast<const float2*>(W2);
        for (int k = t >> 5; k < 256; k += 8) {
            float2 w = w2v[k * 32 + l];          // (W2[k][2l], W2[k][2l+1]) coalesced
            int a = (k >> 2) * 128 + l * 4 + (k & 3);
            sWx[a] = w.x;
            sWy[a] = w.y;
        }
    }
    int base = blockIdx.x * XW2_NODES;
    int cnt = min(XW2_NODES, n - base);
    {
        const uint4* h4 = reinterpret_cast<const uint4*>(g_h1b + (size_t)base * 256);
        for (int i = t; i < cnt * 32; i += 256) {
            uint4 raw = h4[i];
            float* dp = srow + i * 8;
            float2 p0 = __bfloat1622float2(*reinterpret_cast<__nv_bfloat162*>(&raw.x));
            float2 p1 = __bfloat1622float2(*reinterpret_cast<__nv_bfloat162*>(&raw.y));
            float2 p2 = __bfloat1622float2(*reinterpret_cast<__nv_bfloat162*>(&raw.z));
            float2 p3 = __bfloat1622float2(*reinterpret_cast<__nv_bfloat162*>(&raw.w));
            dp[0] = p0.x; dp[1] = p0.y; dp[2] = p1.x; dp[3] = p1.y;
            dp[4] = p2.x; dp[5] = p2.y; dp[6] = p3.x; dp[7] = p3.y;
        }
        for (int i = cnt * 32 + t; i < XW2_NODES * 32; i += 256) {
            float4* dp = reinterpret_cast<float4*>(srow + i * 8);
            dp[0] = make_float4(0, 0, 0, 0);
            dp[1] = make_float4(0, 0, 0, 0);
        }
    }
    __syncthreads();
    int warp = t >> 5;
    int nb = warp * 8;
    const float4* wx4 = reinterpret_cast<const float4*>(sWx);
    const float4* wy4 = reinterpret_cast<const float4*>(sWy);
    const float4* sr4 = reinterpret_cast<const float4*>(srow);
    float2 A0[8], A1[8];
#pragma unroll
    for (int j = 0; j < 8; j++) { A0[j] = make_float2(0, 0); A1[j] = make_float2(0, 0); }
#pragma unroll 2
    for (int kq = 0; kq < 64; kq++) {
        float4 wx = wx4[kq * 32 + l];
        float4 wy = wy4[kq * 32 + l];
        float2 wx01 = make_float2(wx.x, wx.y), wx23 = make_float2(wx.z, wx.w);
        float2 wy01 = make_float2(wy.x, wy.y), wy23 = make_float2(wy.z, wy.w);
#pragma unroll
        for (int j = 0; j < 8; j++) {
            float4 h = sr4[(nb + j) * 64 + kq];
            float2 h01 = make_float2(h.x, h.y), h23 = make_float2(h.z, h.w);
            ffma2(A0[j], h01, wx01);
            ffma2(A0[j], h23, wx23);
            ffma2(A1[j], h01, wy01);
            ffma2(A1[j], h23, wy23);
        }
    }
    float s0 = as2[2 * l], s1 = as2[2 * l + 1];
    float d0 = ad2[2 * l], d1 = ad2[2 * l + 1];
#pragma unroll
    for (int j = 0; j < 8; j++) {
        float a0 = A0[j].x + A0[j].y;
        float a1 = A1[j].x + A1[j].y;
        int node = base + nb + j;
        bool ok = node < n;
        if (ok) {
            *reinterpret_cast<__nv_bfloat162*>(g_xw2b + (size_t)node * 64 + 2 * l) =
                __floats2bfloat162_rn(a0, a1);
        }
        float vs = a0 * s0 + a1 * s1;
        float vd = a0 * d0 + a1 * d1;
#pragma unroll
        for (int o = 16; o; o >>= 1) {
            vs += __shfl_down_sync(0xffffffffu, vs, o);
            vd += __shfl_down_sync(0xffffffffu, vd, o);
        }
        if (l == 0 && ok) { g_als2[node] = vs; g_ald2[node] = vd; }
    }
}

// ---- conv2 gather + fused attention + fused cluster pooling, 2x-unrolled ----
__global__ void k_gather2(const int* __restrict__ assign, int n) {
    __shared__ float sval[64 * 65];
    __shared__ int   sa[64];
    int t = threadIdx.x;            // 1024 threads, 64 nodes/block
    int nl = t >> 4;
    int c = t & 15;
    int node = blockIdx.x * 64 + nl;
    float4 accA = make_float4(0, 0, 0, 0);
    float4 accB = make_float4(0, 0, 0, 0);
    if (node < n) {
        int beg = g_off[node], end = g_off[node + 1];
        float aldv = g_ald2[node];
        float ce4 = g_ce[4];
        float swa = 0.f, swb = 0.f;
        int i = beg;
        for (; i + 2 <= end; i += 2) {
            int2 sdA = g_slot[i];
            int2 sdB = g_slot[i + 1];
            float lgA = g_als2[sdA.x] + aldv + __int_as_float(sdA.y) * ce4;
            float lgB = g_als2[sdB.x] + aldv + __int_as_float(sdB.y) * ce4;
            uint2 rA = *reinterpret_cast<const uint2*>(g_xw2b + (size_t)sdA.x * 64 + c * 4);
            uint2 rB = *reinterpret_cast<const uint2*>(g_xw2b + (size_t)sdB.x * 64 + c * 4);
            float wA = __expf(lrelu(lgA));
            float wB = __expf(lrelu(lgB));
            float2 pA0 = __bfloat1622float2(*reinterpret_cast<__nv_bfloat162*>(&rA.x));
            float2 pA1 = __bfloat1622float2(*reinterpret_cast<__nv_bfloat162*>(&rA.y));
            float2 pB0 = __bfloat1622float2(*reinterpret_cast<__nv_bfloat162*>(&rB.x));
            float2 pB1 = __bfloat1622float2(*reinterpret_cast<__nv_bfloat162*>(&rB.y));
            accA.x = fmaf(wA, pA0.x, accA.x); accA.y = fmaf(wA, pA0.y, accA.y);
            accA.z = fmaf(wA, pA1.x, accA.z); accA.w = fmaf(wA, pA1.y, accA.w);
            accB.x = fmaf(wB, pB0.x, accB.x); accB.y = fmaf(wB, pB0.y, accB.y);
            accB.z = fmaf(wB, pB1.x, accB.z); accB.w = fmaf(wB, pB1.y, accB.w);
            swa += wA; swb += wB;
        }
        if (i < end) {
            int2 sd = g_slot[i];
            float w = __expf(lrelu(g_als2[sd.x] + aldv + __int_as_float(sd.y) * ce4));
            uint2 raw = *reinterpret_cast<const uint2*>(g_xw2b + (size_t)sd.x * 64 + c * 4);
            float2 p0 = __bfloat1622float2(*reinterpret_cast<__nv_bfloat162*>(&raw.x));
            float2 p1 = __bfloat1622float2(*reinterpret_cast<__nv_bfloat162*>(&raw.y));
            accA.x = fmaf(w, p0.x, accA.x); accA.y = fmaf(w, p0.y, accA.y);
            accA.z = fmaf(w, p1.x, accA.z); accA.w = fmaf(w, p1.y, accA.w);
            swa += w;
        }
        accA.x += accB.x; accA.y += accB.y; accA.z += accB.z; accA.w += accB.w;
        float inv = 1.f / (swa + swb + 1e-16f);
        accA.x *= inv; accA.y *= inv; accA.z *= inv; accA.w *= inv;
        if (c == 0) sa[nl] = assign[node];
    } else if (c == 0) {
        sa[nl] = -1;
    }
    float* vp = &sval[nl * 65 + c * 4];
    vp[0] = accA.x; vp[1] = accA.y; vp[2] = accA.z; vp[3] = accA.w;
    __syncthreads();
    if (t < 256) {
        int k = t >> 6, ch = t & 63;
        float s = 0.f;
        for (int j = 0; j < 64; j++) {
            float v = sval[j * 65 + ch];
            if (sa[j] == k) s += v;
        }
        if (s != 0.f) atomicAdd(&g_pool[k * 64 + ch], s);
    }
}

// ---- final: means + MLP + softmax + write output (1 block, 64 threads) ----
__global__ void k_final(const float* __restrict__ b2, const float* __restrict__ A1,
                        const float* __restrict__ c1, const float* __restrict__ A2,
                        const float* __restrict__ c2, float* __restrict__ out) {
    __shared__ float z[4][64];
    __shared__ float red[64];
    __shared__ float logits[4];
    __shared__ float probs[4];
    int t = threadIdx.x;
    float cf[4];
#pragma unroll
    for (int k = 0; k < 4; k++) {
        float cn = g_pool[256 + k];
        z[k][t] = (cn > 0.f) ? (g_pool[k * 64 + t] / cn + b2[t]) : 0.f;
        cf[k] = (cn > 0.f) ? (g_pool[260 + k] / cn) : 0.f;
    }
    __syncthreads();
    for (int k = 0; k < 4; k++) {
        float acc = c1[t];
        for (int i = 0; i < 64; i++) acc = fmaf(z[k][i], A1[i * 64 + t], acc);
        acc = fmaf(cf[k], A1[64 * 64 + t], acc);
        acc = fmaxf(acc, 0.f) * A2[t];
        red[t] = acc;
        __syncthreads();
        if (t == 0) {
            float s = 0.f;
            for (int i = 0; i < 64; i++) s += red[i];
            logits[k] = s + c2[0];
        }
        __syncthreads();
    }
    if (t == 0) {
        float m = fmaxf(fmaxf(logits[0], logits[1]), fmaxf(logits[2], logits[3]));
        float e0 = expf(logits[0] - m), e1 = expf(logits[1] - m);
        float e2 = expf(logits[2] - m), e3 = expf(logits[3] - m);
        float inv = 1.f / (e0 + e1 + e2 + e3);
        probs[0] = e0 * inv; probs[1] = e1 * inv; probs[2] = e2 * inv; probs[3] = e3 * inv;
    }
    __syncthreads();
    if (t < 4) out[t] = probs[t];
#pragma unroll
    for (int k = 0; k < 4; k++) out[4 + k * 64 + t] = z[k][t];
}

extern "C" void kernel_launch(void* const* d_in, const int* in_sizes, int n_in,
                              void* d_out, int out_size) {
    const float* x    = (const float*)d_in[0];
    const int*   ei   = (const int*)d_in[1];
    const float* ea   = (const float*)d_in[2];
    const int*   assign = (const int*)d_in[3];
    const float* W1   = (const float*)d_in[4];
    const float* as1  = (const float*)d_in[5];
    const float* ad1  = (const float*)d_in[6];
    const float* We1  = (const float*)d_in[7];
    const float* ae1  = (const float*)d_in[8];
    const float* b1   = (const float*)d_in[9];
    const float* W2   = (const float*)d_in[10];
    const float* as2  = (const float*)d_in[11];
    const float* ad2  = (const float*)d_in[12];
    const float* We2  = (const float*)d_in[13];
    const float* ae2  = (const float*)d_in[14];
    const float* b2   = (const float*)d_in[15];
    const float* A1   = (const float*)d_in[16];
    const float* c1   = (const float*)d_in[17];
    const float* A2   = (const float*)d_in[18];
    const float* c2   = (const float*)d_in[19];
    float* out = (float*)d_out;

    int n = in_sizes[0] / 7;
    int e = in_sizes[2];
    const int* src = ei;
    const int* dst = ei + e;
    int tot = e + n;
    int nb = (n + SCAN_CHUNK - 1) / SCAN_CHUNK;

    // side stream + events for overlapping xw1 with the CSR-build chain
    static cudaStream_t sB = nullptr;
    static cudaEvent_t evFork = nullptr, evJoin = nullptr;
    if (sB == nullptr) {
        cudaStreamCreateWithFlags(&sB, cudaStreamNonBlocking);
        cudaEventCreateWithFlags(&evFork, cudaEventDisableTiming);
        cudaEventCreateWithFlags(&evJoin, cudaEventDisableTiming);
    }

    cudaEventRecord(evFork, 0);
    cudaStreamWaitEvent(sB, evFork, 0);
    k_xw1<<<(n + 7) / 8, 256, 0, sB>>>(x, W1, as1, ad1, n);
    cudaEventRecord(evJoin, sB);

    k_init<<<208, 256>>>(We1, ae1, We2, ae2, n);
    k_degloop<<<(tot + 255) / 256, 256>>>(dst, ea, x, assign, e, n);
    k_part<<<nb, 1024>>>(n);
    k_offs<<<nb, 1024>>>(n, tot, nb);
    k_fill<<<(tot + 255) / 256, 256>>>(src, dst, ea, e, n);

    cudaStreamWaitEvent(0, evJoin, 0);
    k_gather1<<<(n * 32 + 255) / 256, 256>>>(b1, n);

    cudaFuncSetAttribute(k_xw2, cudaFuncAttributeMaxDynamicSharedMemorySize, 131072);
    k_xw2<<<(n + XW2_NODES - 1) / XW2_NODES, 256, 131072>>>(W2, as2, ad2, n);

    k_gather2<<<(n + 63) / 64, 1024>>>(assign, n);
    k_final<<<1, 64>>>(b2, A1, c1, A2, c2, out);
}